// round 1
// baseline (speedup 1.0000x reference)
#include <cuda_runtime.h>
#include <math_constants.h>

#define NTOK 4096
#define CDIM 1024

// Scratch (allocation-free rule: __device__ globals)
__device__ float g_Q[(size_t)NTOK * CDIM];
__device__ float g_K[(size_t)NTOK * CDIM];
__device__ float g_V[(size_t)NTOK * CDIM];
__device__ float g_S[(size_t)NTOK * NTOK];
__device__ float g_H[(size_t)NTOK * CDIM];

// ---------------------------------------------------------------------------
// Generic 128x128x8 fp32 tiled GEMM.
//   TRANSB=true : Out[M,Nc] = A[M,K] @ B[Nc,K]^T   (dot over contiguous K)
//   TRANSB=false: Out[M,Nc] = A[M,K] @ B[K,Nc]
//   BIAS: += bias[n];  RESID: += resid[m*Nc+n]
// 256 threads, 8x8 per-thread micro-tile, float4 everywhere.
// Requires M%128==0, Nc%128==0, K%8==0 (true for all six calls).
// ---------------------------------------------------------------------------
template <bool TRANSB, bool BIAS, bool RESID>
__global__ __launch_bounds__(256, 2) void gemm128(
    const float* __restrict__ A, const float* __restrict__ B,
    const float* __restrict__ bias, const float* __restrict__ resid,
    float* __restrict__ Out, int M, int Nc, int K)
{
    __shared__ float As[8][128];
    __shared__ float Bs[8][128];

    const int t  = threadIdx.x;
    const int tx = t & 15;        // 0..15  -> 8 output cols
    const int ty = t >> 4;        // 0..15  -> 8 output rows
    const int m0 = blockIdx.y * 128;
    const int n0 = blockIdx.x * 128;

    // A-tile (and TRANSB B-tile) loader indices: 128 rows x 8 k, float4 per thread
    const int arow = t >> 1;          // 0..127
    const int akq  = (t & 1) * 4;     // 0 or 4
    // non-trans B-tile loader: 8 k-rows x 128 cols
    const int brow = t >> 5;          // 0..7
    const int bcol = (t & 31) * 4;    // 0..124

    float acc[8][8];
#pragma unroll
    for (int i = 0; i < 8; ++i)
#pragma unroll
        for (int j = 0; j < 8; ++j) acc[i][j] = 0.0f;

    for (int k0 = 0; k0 < K; k0 += 8) {
        // load A tile (transposed into As[k][m])
        float4 av = *(const float4*)&A[(size_t)(m0 + arow) * K + k0 + akq];
        As[akq + 0][arow] = av.x;
        As[akq + 1][arow] = av.y;
        As[akq + 2][arow] = av.z;
        As[akq + 3][arow] = av.w;

        if (TRANSB) {
            float4 bv = *(const float4*)&B[(size_t)(n0 + arow) * K + k0 + akq];
            Bs[akq + 0][arow] = bv.x;
            Bs[akq + 1][arow] = bv.y;
            Bs[akq + 2][arow] = bv.z;
            Bs[akq + 3][arow] = bv.w;
        } else {
            float4 bv = *(const float4*)&B[(size_t)(k0 + brow) * Nc + n0 + bcol];
            *(float4*)&Bs[brow][bcol] = bv;
        }
        __syncthreads();

#pragma unroll
        for (int k = 0; k < 8; ++k) {
            float a[8], b[8];
            *(float4*)&a[0] = *(const float4*)&As[k][ty * 8];
            *(float4*)&a[4] = *(const float4*)&As[k][ty * 8 + 4];
            *(float4*)&b[0] = *(const float4*)&Bs[k][tx * 8];
            *(float4*)&b[4] = *(const float4*)&Bs[k][tx * 8 + 4];
#pragma unroll
            for (int i = 0; i < 8; ++i)
#pragma unroll
                for (int j = 0; j < 8; ++j)
                    acc[i][j] = fmaf(a[i], b[j], acc[i][j]);
        }
        __syncthreads();
    }

    // epilogue
    float bvals[8];
    if (BIAS) {
        *(float4*)&bvals[0] = *(const float4*)&bias[n0 + tx * 8];
        *(float4*)&bvals[4] = *(const float4*)&bias[n0 + tx * 8 + 4];
    }
#pragma unroll
    for (int i = 0; i < 8; ++i) {
        const int m = m0 + ty * 8 + i;
        const size_t base = (size_t)m * Nc + n0 + tx * 8;
        float o[8];
#pragma unroll
        for (int j = 0; j < 8; ++j) {
            float v = acc[i][j];
            if (BIAS) v += bvals[j];
            o[j] = v;
        }
        if (RESID) {
            float4 r0 = *(const float4*)&resid[base];
            float4 r1 = *(const float4*)&resid[base + 4];
            o[0] += r0.x; o[1] += r0.y; o[2] += r0.z; o[3] += r0.w;
            o[4] += r1.x; o[5] += r1.y; o[6] += r1.z; o[7] += r1.w;
        }
        *(float4*)&Out[base]     = make_float4(o[0], o[1], o[2], o[3]);
        *(float4*)&Out[base + 4] = make_float4(o[4], o[5], o[6], o[7]);
    }
}

// ---------------------------------------------------------------------------
// Row softmax over S[4096][4096], in place. One 512-thread block per row;
// each thread keeps its 8 elements in registers -> 1 read + 1 write of S.
// ---------------------------------------------------------------------------
__device__ __forceinline__ float warpMax(float v) {
#pragma unroll
    for (int o = 16; o > 0; o >>= 1) v = fmaxf(v, __shfl_xor_sync(0xffffffffu, v, o));
    return v;
}
__device__ __forceinline__ float warpSum(float v) {
#pragma unroll
    for (int o = 16; o > 0; o >>= 1) v += __shfl_xor_sync(0xffffffffu, v, o);
    return v;
}

__global__ __launch_bounds__(512) void softmax_rows(float* __restrict__ S)
{
    __shared__ float red[16];
    const int row = blockIdx.x;
    float4* p = (float4*)(S + (size_t)row * NTOK);
    const int t = threadIdx.x;

    float4 v0 = p[t];
    float4 v1 = p[t + 512];

    float m = fmaxf(fmaxf(fmaxf(v0.x, v0.y), fmaxf(v0.z, v0.w)),
                    fmaxf(fmaxf(v1.x, v1.y), fmaxf(v1.z, v1.w)));
    m = warpMax(m);
    if ((t & 31) == 0) red[t >> 5] = m;
    __syncthreads();
    if (t < 32) {
        float z = (t < 16) ? red[t] : -CUDART_INF_F;
        z = warpMax(z);
        if (t == 0) red[0] = z;
    }
    __syncthreads();
    m = red[0];
    __syncthreads();  // everyone has read red[0] before it is reused

    v0.x = __expf(v0.x - m); v0.y = __expf(v0.y - m);
    v0.z = __expf(v0.z - m); v0.w = __expf(v0.w - m);
    v1.x = __expf(v1.x - m); v1.y = __expf(v1.y - m);
    v1.z = __expf(v1.z - m); v1.w = __expf(v1.w - m);

    float s = (v0.x + v0.y + v0.z + v0.w) + (v1.x + v1.y + v1.z + v1.w);
    s = warpSum(s);
    if ((t & 31) == 0) red[t >> 5] = s;
    __syncthreads();
    if (t < 32) {
        float z = (t < 16) ? red[t] : 0.0f;
        z = warpSum(z);
        if (t == 0) red[0] = z;
    }
    __syncthreads();
    const float inv = 1.0f / red[0];

    v0.x *= inv; v0.y *= inv; v0.z *= inv; v0.w *= inv;
    v1.x *= inv; v1.y *= inv; v1.z *= inv; v1.w *= inv;
    p[t] = v0;
    p[t + 512] = v1;
}

// ---------------------------------------------------------------------------
// Launch
// ---------------------------------------------------------------------------
extern "C" void kernel_launch(void* const* d_in, const int* in_sizes, int n_in,
                              void* d_out, int out_size)
{
    const float* x  = (const float*)d_in[0];
    const float* Wq = (const float*)d_in[1];
    const float* bq = (const float*)d_in[2];
    const float* Wk = (const float*)d_in[3];
    const float* bk = (const float*)d_in[4];
    const float* Wv = (const float*)d_in[5];
    const float* bv = (const float*)d_in[6];
    const float* Wo = (const float*)d_in[7];
    const float* bo = (const float*)d_in[8];
    float* out = (float*)d_out;

    float *Q, *K, *V, *S, *H;
    cudaGetSymbolAddress((void**)&Q, g_Q);
    cudaGetSymbolAddress((void**)&K, g_K);
    cudaGetSymbolAddress((void**)&V, g_V);
    cudaGetSymbolAddress((void**)&S, g_S);
    cudaGetSymbolAddress((void**)&H, g_H);

    dim3 blk(256);
    dim3 grid_c(CDIM / 128, NTOK / 128);   // (8, 32)  for Nc=1024 outputs
    dim3 grid_s(NTOK / 128, NTOK / 128);   // (32, 32) for the score matrix

    // Q, K, V = x @ W^T + b
    gemm128<true, true, false><<<grid_c, blk>>>(x, Wq, bq, nullptr, Q, NTOK, CDIM, CDIM);
    gemm128<true, true, false><<<grid_c, blk>>>(x, Wk, bk, nullptr, K, NTOK, CDIM, CDIM);
    gemm128<true, true, false><<<grid_c, blk>>>(x, Wv, bv, nullptr, V, NTOK, CDIM, CDIM);

    // S = Q @ K^T
    gemm128<true, false, false><<<grid_s, blk>>>(Q, K, nullptr, nullptr, S, NTOK, NTOK, CDIM);

    // P = softmax(S) (in place)
    softmax_rows<<<NTOK, 512>>>(S);

    // H = P @ V
    gemm128<false, false, false><<<grid_c, blk>>>(S, V, nullptr, nullptr, H, NTOK, CDIM, NTOK);

    // out = x + H @ Wo^T + bo
    gemm128<true, true, true><<<grid_c, blk>>>(H, Wo, bo, x, out, NTOK, CDIM, CDIM);
}

// round 4
// speedup vs baseline: 2.5120x; 2.5120x over previous
#include <cuda_runtime.h>
#include <cuda_bf16.h>
#include <math_constants.h>
#include <cstdint>

#define NTOK 4096
#define CDIM 1024
#define BM 128
#define BN 128
#define BK 32
#define LDS_A 40   // padded smem row stride (bf16 elems): 80B, conflict-free ldmatrix

// ---------------------------------------------------------------------------
// Scratch (__device__ globals; allocation-free rule)
// ---------------------------------------------------------------------------
__device__ __nv_bfloat16 g_xh[(size_t)NTOK * CDIM], g_xl[(size_t)NTOK * CDIM];
__device__ __nv_bfloat16 g_Wqh[(size_t)CDIM * CDIM], g_Wql[(size_t)CDIM * CDIM];
__device__ __nv_bfloat16 g_Wkh[(size_t)CDIM * CDIM], g_Wkl[(size_t)CDIM * CDIM];
__device__ __nv_bfloat16 g_Wvh[(size_t)CDIM * CDIM], g_Wvl[(size_t)CDIM * CDIM];
__device__ __nv_bfloat16 g_Woh[(size_t)CDIM * CDIM], g_Wol[(size_t)CDIM * CDIM];
__device__ __nv_bfloat16 g_Qh[(size_t)NTOK * CDIM],  g_Ql[(size_t)NTOK * CDIM];
__device__ __nv_bfloat16 g_Kh[(size_t)NTOK * CDIM],  g_Kl[(size_t)NTOK * CDIM];
__device__ __nv_bfloat16 g_Vth[(size_t)CDIM * NTOK], g_Vtl[(size_t)CDIM * NTOK];
__device__ float         g_S[(size_t)NTOK * NTOK];
__device__ __nv_bfloat16 g_Ph[(size_t)NTOK * NTOK],  g_Pl[(size_t)NTOK * NTOK];
__device__ __nv_bfloat16 g_Hh[(size_t)NTOK * CDIM],  g_Hl[(size_t)NTOK * CDIM];

// ---------------------------------------------------------------------------
// PTX helpers (sm_80-compatible only: cp.async / ldmatrix / mma.sync)
// ---------------------------------------------------------------------------
__device__ __forceinline__ uint32_t smem_u32(const void* p) {
    uint32_t a;
    asm("{ .reg .u64 t; cvta.to.shared.u64 t, %1; cvt.u32.u64 %0, t; }" : "=r"(a) : "l"(p));
    return a;
}

__device__ __forceinline__ void cpa16(uint32_t dst, const __nv_bfloat16* src) {
    asm volatile("cp.async.cg.shared.global [%0], [%1], 16;" :: "r"(dst), "l"(src));
}
#define CP_COMMIT() asm volatile("cp.async.commit_group;")
#define CP_WAIT(n)  asm volatile("cp.async.wait_group %0;" :: "n"(n))

#define LDMX4(r, addr) \
    asm volatile("ldmatrix.sync.aligned.m8n8.x4.shared.b16 {%0,%1,%2,%3}, [%4];" \
                 : "=r"((r)[0]), "=r"((r)[1]), "=r"((r)[2]), "=r"((r)[3]) : "r"(addr))

__device__ __forceinline__ void mma16816(float* c, const uint32_t* a, const uint32_t* b) {
    asm volatile(
        "mma.sync.aligned.m16n8k16.row.col.f32.bf16.bf16.f32 "
        "{%0,%1,%2,%3}, {%4,%5,%6,%7}, {%8,%9}, {%0,%1,%2,%3};"
        : "+f"(c[0]), "+f"(c[1]), "+f"(c[2]), "+f"(c[3])
        : "r"(a[0]), "r"(a[1]), "r"(a[2]), "r"(a[3]), "r"(b[0]), "r"(b[1]));
}

// ---------------------------------------------------------------------------
// Generic split-bf16 mma.sync GEMM.  D[m][n] = sum_k A[m,k]*B[n,k] (both K-major)
// MODE: 0=QKV (z selects W/b/out; z==2 scatters V^T), 1=S (fp32 out),
//       2=PV (bf16 split out), 3=O (bias+resid, fp32 out)
// ---------------------------------------------------------------------------
struct GemmArgs {
    const __nv_bfloat16 *Ahi, *Alo;
    const __nv_bfloat16 *Bhi[3], *Blo[3];
    const float* bias[3];
    const float* resid;
    __nv_bfloat16 *Oh[3], *Ol[3];
    float* Of;
    int K;     // reduction length
    int Nout;  // output row stride
};

// tile sizes in bf16 elems / bytes
#define TILE_E (BM * LDS_A)          // 5120 elems per 128x32 tile
#define TILE_B (TILE_E * 2)          // 10240 bytes
#define STAGE_B (4 * TILE_B)         // Ah, Al, Bh, Bl
#define SMEM_TOTAL (2 * STAGE_B)     // 81920

__device__ __forceinline__ void load_tile_async(uint32_t sbase, const __nv_bfloat16* __restrict__ g,
                                                int row0, int K, int kcol, int t) {
#pragma unroll
    for (int i = 0; i < 2; ++i) {
        int id = t + i * 256;
        int row = id >> 2, q = id & 3;
        cpa16(sbase + (uint32_t)(row * LDS_A + q * 8) * 2,
              g + (size_t)(row0 + row) * K + kcol + q * 8);
    }
}

template <int MODE>
__global__ __launch_bounds__(256, 1) void gemm_mma(const GemmArgs p) {
    extern __shared__ __nv_bfloat16 smem[];
    const uint32_t sb = smem_u32(smem);
    const int t = threadIdx.x;
    const int lane = t & 31;
    const int wid = t >> 5;
    const int m0 = blockIdx.y * BM;
    const int n0 = blockIdx.x * BN;
    const int z = (MODE == 0) ? blockIdx.z : 0;
    const __nv_bfloat16* Bhg = p.Bhi[z];
    const __nv_bfloat16* Blg = p.Blo[z];
    const int K = p.K;
    const int nch = K / BK;

    const int warp_m = (wid & 1) * 64;
    const int warp_n = (wid >> 1) * 32;

    // lane-resolved byte offsets within a tile for ldmatrix
    const uint32_t aoff = (uint32_t)((warp_m + (lane & 15)) * LDS_A + (lane >> 4) * 8) * 2;
    const uint32_t boff = (uint32_t)((warp_n + ((lane >> 4) & 1) * 8 + (lane & 7)) * LDS_A
                                     + ((lane >> 3) & 1) * 8) * 2;

    float acc[4][4][4];
#pragma unroll
    for (int i = 0; i < 4; ++i)
#pragma unroll
        for (int j = 0; j < 4; ++j)
#pragma unroll
            for (int r = 0; r < 4; ++r) acc[i][j][r] = 0.0f;

    // prologue: stage 0
    {
        uint32_t s0 = sb;
        load_tile_async(s0 + 0 * TILE_B, p.Ahi, m0, K, 0, t);
        load_tile_async(s0 + 1 * TILE_B, p.Alo, m0, K, 0, t);
        load_tile_async(s0 + 2 * TILE_B, Bhg, n0, K, 0, t);
        load_tile_async(s0 + 3 * TILE_B, Blg, n0, K, 0, t);
        CP_COMMIT();
    }

    for (int c = 0; c < nch; ++c) {
        if (c + 1 < nch) {
            uint32_t s1 = sb + ((c + 1) & 1) * STAGE_B;
            int kc = (c + 1) * BK;
            load_tile_async(s1 + 0 * TILE_B, p.Ahi, m0, K, kc, t);
            load_tile_async(s1 + 1 * TILE_B, p.Alo, m0, K, kc, t);
            load_tile_async(s1 + 2 * TILE_B, Bhg, n0, K, kc, t);
            load_tile_async(s1 + 3 * TILE_B, Blg, n0, K, kc, t);
            CP_COMMIT();
            CP_WAIT(1);
        } else {
            CP_WAIT(0);
        }
        __syncthreads();

        const uint32_t s0 = sb + (c & 1) * STAGE_B;
#pragma unroll
        for (int s = 0; s < 2; ++s) {
            uint32_t ah[4][4], al[4][4], bh[4][2], bl[4][2];
#pragma unroll
            for (int i = 0; i < 4; ++i) {
                const uint32_t ao = (uint32_t)(i * 16 * LDS_A + s * 16) * 2;
                LDMX4(ah[i], s0 + 0 * TILE_B + aoff + ao);
                LDMX4(al[i], s0 + 1 * TILE_B + aoff + ao);
            }
#pragma unroll
            for (int g = 0; g < 2; ++g) {
                const uint32_t bo = (uint32_t)(g * 16 * LDS_A + s * 16) * 2;
                uint32_t r[4];
                LDMX4(r, s0 + 2 * TILE_B + boff + bo);
                bh[2 * g][0] = r[0]; bh[2 * g][1] = r[1];
                bh[2 * g + 1][0] = r[2]; bh[2 * g + 1][1] = r[3];
                LDMX4(r, s0 + 3 * TILE_B + boff + bo);
                bl[2 * g][0] = r[0]; bl[2 * g][1] = r[1];
                bl[2 * g + 1][0] = r[2]; bl[2 * g + 1][1] = r[3];
            }
#pragma unroll
            for (int i = 0; i < 4; ++i)
#pragma unroll
                for (int j = 0; j < 4; ++j) {
                    mma16816(acc[i][j], ah[i], bh[j]);
                    mma16816(acc[i][j], ah[i], bl[j]);
                    mma16816(acc[i][j], al[i], bh[j]);
                }
        }
        __syncthreads();
    }

    // ------------------------------- epilogue ------------------------------
    const float* bias = (MODE == 0) ? p.bias[z] : ((MODE == 3) ? p.bias[0] : nullptr);

#pragma unroll
    for (int i = 0; i < 4; ++i) {
        const int r0 = m0 + warp_m + i * 16 + (lane >> 2);
        const int r1 = r0 + 8;
#pragma unroll
        for (int j = 0; j < 4; ++j) {
            const int cc = n0 + warp_n + j * 8 + (lane & 3) * 2;
            float v0 = acc[i][j][0], v1 = acc[i][j][1];
            float v2 = acc[i][j][2], v3 = acc[i][j][3];

            if (MODE == 1) {
                *(float2*)(p.Of + (size_t)r0 * p.Nout + cc) = make_float2(v0, v1);
                *(float2*)(p.Of + (size_t)r1 * p.Nout + cc) = make_float2(v2, v3);
            } else if (MODE == 3) {
                const float b0 = bias[cc], b1 = bias[cc + 1];
                const float* rs = p.resid;
                float2 ra = *(const float2*)(rs + (size_t)r0 * p.Nout + cc);
                float2 rb = *(const float2*)(rs + (size_t)r1 * p.Nout + cc);
                *(float2*)(p.Of + (size_t)r0 * p.Nout + cc) = make_float2(v0 + b0 + ra.x, v1 + b1 + ra.y);
                *(float2*)(p.Of + (size_t)r1 * p.Nout + cc) = make_float2(v2 + b0 + rb.x, v3 + b1 + rb.y);
            } else {
                if (MODE == 0) {
                    const float b0 = bias[cc], b1 = bias[cc + 1];
                    v0 += b0; v1 += b1; v2 += b0; v3 += b1;
                }
                __nv_bfloat16 h0 = __float2bfloat16(v0), l0 = __float2bfloat16(v0 - __bfloat162float(h0));
                __nv_bfloat16 h1 = __float2bfloat16(v1), l1 = __float2bfloat16(v1 - __bfloat162float(h1));
                __nv_bfloat16 h2 = __float2bfloat16(v2), l2 = __float2bfloat16(v2 - __bfloat162float(h2));
                __nv_bfloat16 h3 = __float2bfloat16(v3), l3 = __float2bfloat16(v3 - __bfloat162float(h3));
                if (MODE == 0 && z == 2) {
                    // scatter transposed: Vt[channel][token]
                    __nv_bfloat16* oh = p.Oh[2];
                    __nv_bfloat16* ol = p.Ol[2];
                    oh[(size_t)cc * NTOK + r0] = h0;       ol[(size_t)cc * NTOK + r0] = l0;
                    oh[(size_t)(cc + 1) * NTOK + r0] = h1; ol[(size_t)(cc + 1) * NTOK + r0] = l1;
                    oh[(size_t)cc * NTOK + r1] = h2;       ol[(size_t)cc * NTOK + r1] = l2;
                    oh[(size_t)(cc + 1) * NTOK + r1] = h3; ol[(size_t)(cc + 1) * NTOK + r1] = l3;
                } else {
                    __nv_bfloat16* oh = p.Oh[z];
                    __nv_bfloat16* ol = p.Ol[z];
                    *(__nv_bfloat162*)(oh + (size_t)r0 * p.Nout + cc) = __nv_bfloat162(h0, h1);
                    *(__nv_bfloat162*)(oh + (size_t)r1 * p.Nout + cc) = __nv_bfloat162(h2, h3);
                    *(__nv_bfloat162*)(ol + (size_t)r0 * p.Nout + cc) = __nv_bfloat162(l0, l1);
                    *(__nv_bfloat162*)(ol + (size_t)r1 * p.Nout + cc) = __nv_bfloat162(l2, l3);
                }
            }
        }
    }
}

// ---------------------------------------------------------------------------
// fp32 -> (hi, lo) bf16 split
// ---------------------------------------------------------------------------
__global__ __launch_bounds__(256) void split_f32(const float4* __restrict__ in,
                                                 __nv_bfloat16* __restrict__ hi,
                                                 __nv_bfloat16* __restrict__ lo, int n4) {
    int i = blockIdx.x * 256 + threadIdx.x;
    if (i >= n4) return;
    float4 v = in[i];
    float vv[4] = {v.x, v.y, v.z, v.w};
    __nv_bfloat16 h[4], l[4];
#pragma unroll
    for (int j = 0; j < 4; ++j) {
        h[j] = __float2bfloat16(vv[j]);
        l[j] = __float2bfloat16(vv[j] - __bfloat162float(h[j]));
    }
    *(__nv_bfloat162*)(hi + (size_t)i * 4)     = __nv_bfloat162(h[0], h[1]);
    *(__nv_bfloat162*)(hi + (size_t)i * 4 + 2) = __nv_bfloat162(h[2], h[3]);
    *(__nv_bfloat162*)(lo + (size_t)i * 4)     = __nv_bfloat162(l[0], l[1]);
    *(__nv_bfloat162*)(lo + (size_t)i * 4 + 2) = __nv_bfloat162(l[2], l[3]);
}

// ---------------------------------------------------------------------------
// Row softmax: S fp32 [4096] -> P hi/lo bf16
// ---------------------------------------------------------------------------
__device__ __forceinline__ float warpMax(float v) {
#pragma unroll
    for (int o = 16; o > 0; o >>= 1) v = fmaxf(v, __shfl_xor_sync(0xffffffffu, v, o));
    return v;
}
__device__ __forceinline__ float warpSum(float v) {
#pragma unroll
    for (int o = 16; o > 0; o >>= 1) v += __shfl_xor_sync(0xffffffffu, v, o);
    return v;
}

__global__ __launch_bounds__(512) void softmax_rows(const float* __restrict__ S,
                                                    __nv_bfloat16* __restrict__ Ph,
                                                    __nv_bfloat16* __restrict__ Pl) {
    __shared__ float red[16];
    const int row = blockIdx.x;
    const float4* p = (const float4*)(S + (size_t)row * NTOK);
    const int t = threadIdx.x;

    float4 v0 = p[t];
    float4 v1 = p[t + 512];

    float m = fmaxf(fmaxf(fmaxf(v0.x, v0.y), fmaxf(v0.z, v0.w)),
                    fmaxf(fmaxf(v1.x, v1.y), fmaxf(v1.z, v1.w)));
    m = warpMax(m);
    if ((t & 31) == 0) red[t >> 5] = m;
    __syncthreads();
    if (t < 32) {
        float zz = (t < 16) ? red[t] : -CUDART_INF_F;
        zz = warpMax(zz);
        if (t == 0) red[0] = zz;
    }
    __syncthreads();
    m = red[0];
    __syncthreads();

    v0.x = __expf(v0.x - m); v0.y = __expf(v0.y - m);
    v0.z = __expf(v0.z - m); v0.w = __expf(v0.w - m);
    v1.x = __expf(v1.x - m); v1.y = __expf(v1.y - m);
    v1.z = __expf(v1.z - m); v1.w = __expf(v1.w - m);

    float s = (v0.x + v0.y + v0.z + v0.w) + (v1.x + v1.y + v1.z + v1.w);
    s = warpSum(s);
    if ((t & 31) == 0) red[t >> 5] = s;
    __syncthreads();
    if (t < 32) {
        float zz = (t < 16) ? red[t] : 0.0f;
        zz = warpSum(zz);
        if (t == 0) red[0] = zz;
    }
    __syncthreads();
    const float inv = 1.0f / red[0];

    float pv[8] = {v0.x * inv, v0.y * inv, v0.z * inv, v0.w * inv,
                   v1.x * inv, v1.y * inv, v1.z * inv, v1.w * inv};
    __nv_bfloat16 h[8], l[8];
#pragma unroll
    for (int j = 0; j < 8; ++j) {
        h[j] = __float2bfloat16(pv[j]);
        l[j] = __float2bfloat16(pv[j] - __bfloat162float(h[j]));
    }
    size_t base = (size_t)row * NTOK;
    *(__nv_bfloat162*)(Ph + base + 4 * t)            = __nv_bfloat162(h[0], h[1]);
    *(__nv_bfloat162*)(Ph + base + 4 * t + 2)        = __nv_bfloat162(h[2], h[3]);
    *(__nv_bfloat162*)(Ph + base + 2048 + 4 * t)     = __nv_bfloat162(h[4], h[5]);
    *(__nv_bfloat162*)(Ph + base + 2048 + 4 * t + 2) = __nv_bfloat162(h[6], h[7]);
    *(__nv_bfloat162*)(Pl + base + 4 * t)            = __nv_bfloat162(l[0], l[1]);
    *(__nv_bfloat162*)(Pl + base + 4 * t + 2)        = __nv_bfloat162(l[2], l[3]);
    *(__nv_bfloat162*)(Pl + base + 2048 + 4 * t)     = __nv_bfloat162(l[4], l[5]);
    *(__nv_bfloat162*)(Pl + base + 2048 + 4 * t + 2) = __nv_bfloat162(l[6], l[7]);
}

// ---------------------------------------------------------------------------
// Launch
// ---------------------------------------------------------------------------
static void* sym(const void* s) { void* p; cudaGetSymbolAddress(&p, s); return p; }

extern "C" void kernel_launch(void* const* d_in, const int* in_sizes, int n_in,
                              void* d_out, int out_size) {
    const float* x  = (const float*)d_in[0];
    const float* Wq = (const float*)d_in[1];
    const float* bq = (const float*)d_in[2];
    const float* Wk = (const float*)d_in[3];
    const float* bk = (const float*)d_in[4];
    const float* Wv = (const float*)d_in[5];
    const float* bv = (const float*)d_in[6];
    const float* Wo = (const float*)d_in[7];
    const float* bo = (const float*)d_in[8];
    float* out = (float*)d_out;

    __nv_bfloat16* xh  = (__nv_bfloat16*)sym(g_xh);
    __nv_bfloat16* xl  = (__nv_bfloat16*)sym(g_xl);
    __nv_bfloat16* Wqh = (__nv_bfloat16*)sym(g_Wqh);
    __nv_bfloat16* Wql = (__nv_bfloat16*)sym(g_Wql);
    __nv_bfloat16* Wkh = (__nv_bfloat16*)sym(g_Wkh);
    __nv_bfloat16* Wkl = (__nv_bfloat16*)sym(g_Wkl);
    __nv_bfloat16* Wvh = (__nv_bfloat16*)sym(g_Wvh);
    __nv_bfloat16* Wvl = (__nv_bfloat16*)sym(g_Wvl);
    __nv_bfloat16* Woh = (__nv_bfloat16*)sym(g_Woh);
    __nv_bfloat16* Wol = (__nv_bfloat16*)sym(g_Wol);
    __nv_bfloat16* Qh  = (__nv_bfloat16*)sym(g_Qh);
    __nv_bfloat16* Ql  = (__nv_bfloat16*)sym(g_Ql);
    __nv_bfloat16* Kh  = (__nv_bfloat16*)sym(g_Kh);
    __nv_bfloat16* Kl  = (__nv_bfloat16*)sym(g_Kl);
    __nv_bfloat16* Vth = (__nv_bfloat16*)sym(g_Vth);
    __nv_bfloat16* Vtl = (__nv_bfloat16*)sym(g_Vtl);
    float*         S   = (float*)sym(g_S);
    __nv_bfloat16* Ph  = (__nv_bfloat16*)sym(g_Ph);
    __nv_bfloat16* Pl  = (__nv_bfloat16*)sym(g_Pl);
    __nv_bfloat16* Hh  = (__nv_bfloat16*)sym(g_Hh);
    __nv_bfloat16* Hl  = (__nv_bfloat16*)sym(g_Hl);

    cudaFuncSetAttribute(gemm_mma<0>, cudaFuncAttributeMaxDynamicSharedMemorySize, SMEM_TOTAL);
    cudaFuncSetAttribute(gemm_mma<1>, cudaFuncAttributeMaxDynamicSharedMemorySize, SMEM_TOTAL);
    cudaFuncSetAttribute(gemm_mma<2>, cudaFuncAttributeMaxDynamicSharedMemorySize, SMEM_TOTAL);
    cudaFuncSetAttribute(gemm_mma<3>, cudaFuncAttributeMaxDynamicSharedMemorySize, SMEM_TOTAL);

    // splits
    split_f32<<<(NTOK * CDIM / 4 + 255) / 256, 256>>>((const float4*)x, xh, xl, NTOK * CDIM / 4);
    split_f32<<<(CDIM * CDIM / 4 + 255) / 256, 256>>>((const float4*)Wq, Wqh, Wql, CDIM * CDIM / 4);
    split_f32<<<(CDIM * CDIM / 4 + 255) / 256, 256>>>((const float4*)Wk, Wkh, Wkl, CDIM * CDIM / 4);
    split_f32<<<(CDIM * CDIM / 4 + 255) / 256, 256>>>((const float4*)Wv, Wvh, Wvl, CDIM * CDIM / 4);
    split_f32<<<(CDIM * CDIM / 4 + 255) / 256, 256>>>((const float4*)Wo, Woh, Wol, CDIM * CDIM / 4);

    // QKV (fused over z): Q/K row-major, V scattered transposed
    GemmArgs a = {};
    a.Ahi = xh; a.Alo = xl;
    a.Bhi[0] = Wqh; a.Blo[0] = Wql; a.Bhi[1] = Wkh; a.Blo[1] = Wkl; a.Bhi[2] = Wvh; a.Blo[2] = Wvl;
    a.bias[0] = bq; a.bias[1] = bk; a.bias[2] = bv;
    a.Oh[0] = Qh; a.Ol[0] = Ql; a.Oh[1] = Kh; a.Ol[1] = Kl; a.Oh[2] = Vth; a.Ol[2] = Vtl;
    a.K = CDIM; a.Nout = CDIM;
    gemm_mma<0><<<dim3(CDIM / BN, NTOK / BM, 3), 256, SMEM_TOTAL>>>(a);

    // S = Q @ K^T  (fp32 out)
    GemmArgs as = {};
    as.Ahi = Qh; as.Alo = Ql; as.Bhi[0] = Kh; as.Blo[0] = Kl;
    as.Of = S; as.K = CDIM; as.Nout = NTOK;
    gemm_mma<1><<<dim3(NTOK / BN, NTOK / BM, 1), 256, SMEM_TOTAL>>>(as);

    // P = softmax(S) -> bf16 hi/lo
    softmax_rows<<<NTOK, 512>>>(S, Ph, Pl);

    // H = P @ V  (B = V^T, K-major over tokens)
    GemmArgs ap = {};
    ap.Ahi = Ph; ap.Alo = Pl; ap.Bhi[0] = Vth; ap.Blo[0] = Vtl;
    ap.Oh[0] = Hh; ap.Ol[0] = Hl; ap.K = NTOK; ap.Nout = CDIM;
    gemm_mma<2><<<dim3(CDIM / BN, NTOK / BM, 1), 256, SMEM_TOTAL>>>(ap);

    // out = x + H @ Wo^T + bo
    GemmArgs ao = {};
    ao.Ahi = Hh; ao.Alo = Hl; ao.Bhi[0] = Woh; ao.Blo[0] = Wol;
    ao.bias[0] = bo; ao.resid = x; ao.Of = out; ao.K = CDIM; ao.Nout = CDIM;
    gemm_mma<3><<<dim3(CDIM / BN, NTOK / BM, 1), 256, SMEM_TOTAL>>>(ao);
}

// round 5
// speedup vs baseline: 2.5429x; 1.0123x over previous
#include <cuda_runtime.h>
#include <cuda_bf16.h>
#include <math_constants.h>
#include <cstdint>

#define NTOK 4096
#define CDIM 1024
#define BM 128
#define BN 128
#define BK 32
#define LDS_A 40   // padded smem row stride (bf16 elems): 80B, conflict-free ldmatrix

// ---------------------------------------------------------------------------
// Scratch (__device__ globals; allocation-free rule)
// ---------------------------------------------------------------------------
__device__ __nv_bfloat16 g_xh[(size_t)NTOK * CDIM], g_xl[(size_t)NTOK * CDIM];
__device__ __nv_bfloat16 g_Wqh[(size_t)CDIM * CDIM], g_Wql[(size_t)CDIM * CDIM];
__device__ __nv_bfloat16 g_Wkh[(size_t)CDIM * CDIM], g_Wkl[(size_t)CDIM * CDIM];
__device__ __nv_bfloat16 g_Wvh[(size_t)CDIM * CDIM], g_Wvl[(size_t)CDIM * CDIM];
__device__ __nv_bfloat16 g_Woh[(size_t)CDIM * CDIM], g_Wol[(size_t)CDIM * CDIM];
__device__ __nv_bfloat16 g_Qh[(size_t)NTOK * CDIM],  g_Ql[(size_t)NTOK * CDIM];
__device__ __nv_bfloat16 g_Kh[(size_t)NTOK * CDIM],  g_Kl[(size_t)NTOK * CDIM];
__device__ __nv_bfloat16 g_Vth[(size_t)CDIM * NTOK], g_Vtl[(size_t)CDIM * NTOK];
__device__ float         g_S[(size_t)NTOK * NTOK];
__device__ __nv_bfloat16 g_Ph[(size_t)NTOK * NTOK],  g_Pl[(size_t)NTOK * NTOK];
__device__ __nv_bfloat16 g_Hh[(size_t)NTOK * CDIM],  g_Hl[(size_t)NTOK * CDIM];

// ---------------------------------------------------------------------------
// PTX helpers (sm_80-compatible only: cp.async / ldmatrix / mma.sync)
// ---------------------------------------------------------------------------
__device__ __forceinline__ uint32_t smem_u32(const void* p) {
    uint32_t a;
    asm("{ .reg .u64 t; cvta.to.shared.u64 t, %1; cvt.u32.u64 %0, t; }" : "=r"(a) : "l"(p));
    return a;
}

__device__ __forceinline__ void cpa16(uint32_t dst, const __nv_bfloat16* src) {
    asm volatile("cp.async.cg.shared.global [%0], [%1], 16;" :: "r"(dst), "l"(src));
}
#define CP_COMMIT() asm volatile("cp.async.commit_group;")
#define CP_WAIT(n)  asm volatile("cp.async.wait_group %0;" :: "n"(n))

#define LDMX4(r, addr) \
    asm volatile("ldmatrix.sync.aligned.m8n8.x4.shared.b16 {%0,%1,%2,%3}, [%4];" \
                 : "=r"((r)[0]), "=r"((r)[1]), "=r"((r)[2]), "=r"((r)[3]) : "r"(addr))

__device__ __forceinline__ void mma16816(float* c, const uint32_t* a, const uint32_t* b) {
    asm volatile(
        "mma.sync.aligned.m16n8k16.row.col.f32.bf16.bf16.f32 "
        "{%0,%1,%2,%3}, {%4,%5,%6,%7}, {%8,%9}, {%0,%1,%2,%3};"
        : "+f"(c[0]), "+f"(c[1]), "+f"(c[2]), "+f"(c[3])
        : "r"(a[0]), "r"(a[1]), "r"(a[2]), "r"(a[3]), "r"(b[0]), "r"(b[1]));
}

// ---------------------------------------------------------------------------
// Generic split-bf16 mma.sync GEMM.  D[m][n] = sum_k A[m,k]*B[n,k] (both K-major)
// MODE: 0=QKV (z selects W/b/out; z==2 scatters V^T), 1=S (fp32 out),
//       2=PV (bf16 split out), 3=O (bias+resid, fp32 out)
// ---------------------------------------------------------------------------
struct GemmArgs {
    const __nv_bfloat16 *Ahi, *Alo;
    const __nv_bfloat16 *Bhi[3], *Blo[3];
    const float* bias[3];
    const float* resid;
    __nv_bfloat16 *Oh[3], *Ol[3];
    float* Of;
    int K;     // reduction length
    int Nout;  // output row stride
};

// tile sizes in bf16 elems / bytes
#define TILE_E (BM * LDS_A)          // 5120 elems per 128x32 tile
#define TILE_B (TILE_E * 2)          // 10240 bytes
#define STAGE_B (4 * TILE_B)         // Ah, Al, Bh, Bl  (40960)
#define NSTAGE 3
#define SMEM_TOTAL (NSTAGE * STAGE_B)  // 122880

__device__ __forceinline__ void load_tile_async(uint32_t sbase, const __nv_bfloat16* __restrict__ g,
                                                int row0, int K, int kcol, int t) {
#pragma unroll
    for (int i = 0; i < 2; ++i) {
        int id = t + i * 256;
        int row = id >> 2, q = id & 3;
        cpa16(sbase + (uint32_t)(row * LDS_A + q * 8) * 2,
              g + (size_t)(row0 + row) * K + kcol + q * 8);
    }
}

template <int MODE>
__global__ __launch_bounds__(256, 1) void gemm_mma(const GemmArgs p) {
    extern __shared__ __nv_bfloat16 smem[];
    const uint32_t sb = smem_u32(smem);
    const int t = threadIdx.x;
    const int lane = t & 31;
    const int wid = t >> 5;
    const int m0 = blockIdx.y * BM;
    const int n0 = blockIdx.x * BN;
    const int z = (MODE == 0) ? blockIdx.z : 0;
    const __nv_bfloat16* Bhg = p.Bhi[z];
    const __nv_bfloat16* Blg = p.Blo[z];
    const int K = p.K;
    const int nch = K / BK;

    const int warp_m = (wid & 1) * 64;
    const int warp_n = (wid >> 1) * 32;

    // lane-resolved byte offsets within a tile for ldmatrix
    const uint32_t aoff = (uint32_t)((warp_m + (lane & 15)) * LDS_A + (lane >> 4) * 8) * 2;
    const uint32_t boff = (uint32_t)((warp_n + ((lane >> 4) & 1) * 8 + (lane & 7)) * LDS_A
                                     + ((lane >> 3) & 1) * 8) * 2;

    float acc[4][4][4];
#pragma unroll
    for (int i = 0; i < 4; ++i)
#pragma unroll
        for (int j = 0; j < 4; ++j)
#pragma unroll
            for (int r = 0; r < 4; ++r) acc[i][j][r] = 0.0f;

    // prologue: stages 0 and 1
#pragma unroll
    for (int s = 0; s < 2; ++s) {
        uint32_t sg = sb + s * STAGE_B;
        int kc = s * BK;
        load_tile_async(sg + 0 * TILE_B, p.Ahi, m0, K, kc, t);
        load_tile_async(sg + 1 * TILE_B, p.Alo, m0, K, kc, t);
        load_tile_async(sg + 2 * TILE_B, Bhg, n0, K, kc, t);
        load_tile_async(sg + 3 * TILE_B, Blg, n0, K, kc, t);
        CP_COMMIT();
    }

    int slot = 0;       // slot of chunk c  (c % 3)
    int slot2 = 2;      // slot of chunk c+2
    for (int c = 0; c < nch; ++c) {
        if (c + 1 < nch) { CP_WAIT(1); } else { CP_WAIT(0); }
        __syncthreads();

        if (c + 2 < nch) {
            uint32_t sg = sb + slot2 * STAGE_B;
            int kc = (c + 2) * BK;
            load_tile_async(sg + 0 * TILE_B, p.Ahi, m0, K, kc, t);
            load_tile_async(sg + 1 * TILE_B, p.Alo, m0, K, kc, t);
            load_tile_async(sg + 2 * TILE_B, Bhg, n0, K, kc, t);
            load_tile_async(sg + 3 * TILE_B, Blg, n0, K, kc, t);
            CP_COMMIT();
        }

        const uint32_t s0 = sb + slot * STAGE_B;
#pragma unroll
        for (int s = 0; s < 2; ++s) {
            uint32_t ah[4][4], al[4][4], bh[4][2], bl[4][2];
#pragma unroll
            for (int i = 0; i < 4; ++i) {
                const uint32_t ao = (uint32_t)(i * 16 * LDS_A + s * 16) * 2;
                LDMX4(ah[i], s0 + 0 * TILE_B + aoff + ao);
                LDMX4(al[i], s0 + 1 * TILE_B + aoff + ao);
            }
#pragma unroll
            for (int g = 0; g < 2; ++g) {
                const uint32_t bo = (uint32_t)(g * 16 * LDS_A + s * 16) * 2;
                uint32_t r[4];
                LDMX4(r, s0 + 2 * TILE_B + boff + bo);
                bh[2 * g][0] = r[0]; bh[2 * g][1] = r[1];
                bh[2 * g + 1][0] = r[2]; bh[2 * g + 1][1] = r[3];
                LDMX4(r, s0 + 3 * TILE_B + boff + bo);
                bl[2 * g][0] = r[0]; bl[2 * g][1] = r[1];
                bl[2 * g + 1][0] = r[2]; bl[2 * g + 1][1] = r[3];
            }
            // product-major ordering: consecutive HMMAs hit different accumulators
#pragma unroll
            for (int i = 0; i < 4; ++i)
#pragma unroll
                for (int j = 0; j < 4; ++j)
                    mma16816(acc[i][j], ah[i], bh[j]);
#pragma unroll
            for (int i = 0; i < 4; ++i)
#pragma unroll
                for (int j = 0; j < 4; ++j)
                    mma16816(acc[i][j], ah[i], bl[j]);
#pragma unroll
            for (int i = 0; i < 4; ++i)
#pragma unroll
                for (int j = 0; j < 4; ++j)
                    mma16816(acc[i][j], al[i], bh[j]);
        }
        slot = (slot + 1 == NSTAGE) ? 0 : slot + 1;
        slot2 = (slot2 + 1 == NSTAGE) ? 0 : slot2 + 1;
    }

    // ------------------------------- epilogue ------------------------------
    const float* bias = (MODE == 0) ? p.bias[z] : ((MODE == 3) ? p.bias[0] : nullptr);

#pragma unroll
    for (int i = 0; i < 4; ++i) {
        const int r0 = m0 + warp_m + i * 16 + (lane >> 2);
        const int r1 = r0 + 8;
#pragma unroll
        for (int j = 0; j < 4; ++j) {
            const int cc = n0 + warp_n + j * 8 + (lane & 3) * 2;
            float v0 = acc[i][j][0], v1 = acc[i][j][1];
            float v2 = acc[i][j][2], v3 = acc[i][j][3];

            if (MODE == 1) {
                *(float2*)(p.Of + (size_t)r0 * p.Nout + cc) = make_float2(v0, v1);
                *(float2*)(p.Of + (size_t)r1 * p.Nout + cc) = make_float2(v2, v3);
            } else if (MODE == 3) {
                const float b0 = bias[cc], b1 = bias[cc + 1];
                const float* rs = p.resid;
                float2 ra = *(const float2*)(rs + (size_t)r0 * p.Nout + cc);
                float2 rb = *(const float2*)(rs + (size_t)r1 * p.Nout + cc);
                *(float2*)(p.Of + (size_t)r0 * p.Nout + cc) = make_float2(v0 + b0 + ra.x, v1 + b1 + ra.y);
                *(float2*)(p.Of + (size_t)r1 * p.Nout + cc) = make_float2(v2 + b0 + rb.x, v3 + b1 + rb.y);
            } else {
                if (MODE == 0) {
                    const float b0 = bias[cc], b1 = bias[cc + 1];
                    v0 += b0; v1 += b1; v2 += b0; v3 += b1;
                }
                __nv_bfloat16 h0 = __float2bfloat16(v0), l0 = __float2bfloat16(v0 - __bfloat162float(h0));
                __nv_bfloat16 h1 = __float2bfloat16(v1), l1 = __float2bfloat16(v1 - __bfloat162float(h1));
                __nv_bfloat16 h2 = __float2bfloat16(v2), l2 = __float2bfloat16(v2 - __bfloat162float(h2));
                __nv_bfloat16 h3 = __float2bfloat16(v3), l3 = __float2bfloat16(v3 - __bfloat162float(h3));
                if (MODE == 0 && z == 2) {
                    // scatter transposed: Vt[channel][token]
                    __nv_bfloat16* oh = p.Oh[2];
                    __nv_bfloat16* ol = p.Ol[2];
                    oh[(size_t)cc * NTOK + r0] = h0;       ol[(size_t)cc * NTOK + r0] = l0;
                    oh[(size_t)(cc + 1) * NTOK + r0] = h1; ol[(size_t)(cc + 1) * NTOK + r0] = l1;
                    oh[(size_t)cc * NTOK + r1] = h2;       ol[(size_t)cc * NTOK + r1] = l2;
                    oh[(size_t)(cc + 1) * NTOK + r1] = h3; ol[(size_t)(cc + 1) * NTOK + r1] = l3;
                } else {
                    __nv_bfloat16* oh = p.Oh[z];
                    __nv_bfloat16* ol = p.Ol[z];
                    *(__nv_bfloat162*)(oh + (size_t)r0 * p.Nout + cc) = __nv_bfloat162(h0, h1);
                    *(__nv_bfloat162*)(oh + (size_t)r1 * p.Nout + cc) = __nv_bfloat162(h2, h3);
                    *(__nv_bfloat162*)(ol + (size_t)r0 * p.Nout + cc) = __nv_bfloat162(l0, l1);
                    *(__nv_bfloat162*)(ol + (size_t)r1 * p.Nout + cc) = __nv_bfloat162(l2, l3);
                }
            }
        }
    }
}

// ---------------------------------------------------------------------------
// fp32 -> (hi, lo) bf16 split
// ---------------------------------------------------------------------------
__global__ __launch_bounds__(256) void split_f32(const float4* __restrict__ in,
                                                 __nv_bfloat16* __restrict__ hi,
                                                 __nv_bfloat16* __restrict__ lo, int n4) {
    int i = blockIdx.x * 256 + threadIdx.x;
    if (i >= n4) return;
    float4 v = in[i];
    float vv[4] = {v.x, v.y, v.z, v.w};
    __nv_bfloat16 h[4], l[4];
#pragma unroll
    for (int j = 0; j < 4; ++j) {
        h[j] = __float2bfloat16(vv[j]);
        l[j] = __float2bfloat16(vv[j] - __bfloat162float(h[j]));
    }
    *(__nv_bfloat162*)(hi + (size_t)i * 4)     = __nv_bfloat162(h[0], h[1]);
    *(__nv_bfloat162*)(hi + (size_t)i * 4 + 2) = __nv_bfloat162(h[2], h[3]);
    *(__nv_bfloat162*)(lo + (size_t)i * 4)     = __nv_bfloat162(l[0], l[1]);
    *(__nv_bfloat162*)(lo + (size_t)i * 4 + 2) = __nv_bfloat162(l[2], l[3]);
}

// ---------------------------------------------------------------------------
// Row softmax: S fp32 [4096] -> P hi/lo bf16
// ---------------------------------------------------------------------------
__device__ __forceinline__ float warpMax(float v) {
#pragma unroll
    for (int o = 16; o > 0; o >>= 1) v = fmaxf(v, __shfl_xor_sync(0xffffffffu, v, o));
    return v;
}
__device__ __forceinline__ float warpSum(float v) {
#pragma unroll
    for (int o = 16; o > 0; o >>= 1) v += __shfl_xor_sync(0xffffffffu, v, o);
    return v;
}

__global__ __launch_bounds__(512) void softmax_rows(const float* __restrict__ S,
                                                    __nv_bfloat16* __restrict__ Ph,
                                                    __nv_bfloat16* __restrict__ Pl) {
    __shared__ float red[16];
    const int row = blockIdx.x;
    const float4* p = (const float4*)(S + (size_t)row * NTOK);
    const int t = threadIdx.x;

    float4 v0 = p[t];
    float4 v1 = p[t + 512];

    float m = fmaxf(fmaxf(fmaxf(v0.x, v0.y), fmaxf(v0.z, v0.w)),
                    fmaxf(fmaxf(v1.x, v1.y), fmaxf(v1.z, v1.w)));
    m = warpMax(m);
    if ((t & 31) == 0) red[t >> 5] = m;
    __syncthreads();
    if (t < 32) {
        float zz = (t < 16) ? red[t] : -CUDART_INF_F;
        zz = warpMax(zz);
        if (t == 0) red[0] = zz;
    }
    __syncthreads();
    m = red[0];
    __syncthreads();

    v0.x = __expf(v0.x - m); v0.y = __expf(v0.y - m);
    v0.z = __expf(v0.z - m); v0.w = __expf(v0.w - m);
    v1.x = __expf(v1.x - m); v1.y = __expf(v1.y - m);
    v1.z = __expf(v1.z - m); v1.w = __expf(v1.w - m);

    float s = (v0.x + v0.y + v0.z + v0.w) + (v1.x + v1.y + v1.z + v1.w);
    s = warpSum(s);
    if ((t & 31) == 0) red[t >> 5] = s;
    __syncthreads();
    if (t < 32) {
        float zz = (t < 16) ? red[t] : 0.0f;
        zz = warpSum(zz);
        if (t == 0) red[0] = zz;
    }
    __syncthreads();
    const float inv = 1.0f / red[0];

    float pv[8] = {v0.x * inv, v0.y * inv, v0.z * inv, v0.w * inv,
                   v1.x * inv, v1.y * inv, v1.z * inv, v1.w * inv};
    __nv_bfloat16 h[8], l[8];
#pragma unroll
    for (int j = 0; j < 8; ++j) {
        h[j] = __float2bfloat16(pv[j]);
        l[j] = __float2bfloat16(pv[j] - __bfloat162float(h[j]));
    }
    size_t base = (size_t)row * NTOK;
    *(__nv_bfloat162*)(Ph + base + 4 * t)            = __nv_bfloat162(h[0], h[1]);
    *(__nv_bfloat162*)(Ph + base + 4 * t + 2)        = __nv_bfloat162(h[2], h[3]);
    *(__nv_bfloat162*)(Ph + base + 2048 + 4 * t)     = __nv_bfloat162(h[4], h[5]);
    *(__nv_bfloat162*)(Ph + base + 2048 + 4 * t + 2) = __nv_bfloat162(h[6], h[7]);
    *(__nv_bfloat162*)(Pl + base + 4 * t)            = __nv_bfloat162(l[0], l[1]);
    *(__nv_bfloat162*)(Pl + base + 4 * t + 2)        = __nv_bfloat162(l[2], l[3]);
    *(__nv_bfloat162*)(Pl + base + 2048 + 4 * t)     = __nv_bfloat162(l[4], l[5]);
    *(__nv_bfloat162*)(Pl + base + 2048 + 4 * t + 2) = __nv_bfloat162(l[6], l[7]);
}

// ---------------------------------------------------------------------------
// Launch
// ---------------------------------------------------------------------------
static void* sym(const void* s) { void* p; cudaGetSymbolAddress(&p, s); return p; }

extern "C" void kernel_launch(void* const* d_in, const int* in_sizes, int n_in,
                              void* d_out, int out_size) {
    const float* x  = (const float*)d_in[0];
    const float* Wq = (const float*)d_in[1];
    const float* bq = (const float*)d_in[2];
    const float* Wk = (const float*)d_in[3];
    const float* bk = (const float*)d_in[4];
    const float* Wv = (const float*)d_in[5];
    const float* bv = (const float*)d_in[6];
    const float* Wo = (const float*)d_in[7];
    const float* bo = (const float*)d_in[8];
    float* out = (float*)d_out;

    __nv_bfloat16* xh  = (__nv_bfloat16*)sym(g_xh);
    __nv_bfloat16* xl  = (__nv_bfloat16*)sym(g_xl);
    __nv_bfloat16* Wqh = (__nv_bfloat16*)sym(g_Wqh);
    __nv_bfloat16* Wql = (__nv_bfloat16*)sym(g_Wql);
    __nv_bfloat16* Wkh = (__nv_bfloat16*)sym(g_Wkh);
    __nv_bfloat16* Wkl = (__nv_bfloat16*)sym(g_Wkl);
    __nv_bfloat16* Wvh = (__nv_bfloat16*)sym(g_Wvh);
    __nv_bfloat16* Wvl = (__nv_bfloat16*)sym(g_Wvl);
    __nv_bfloat16* Woh = (__nv_bfloat16*)sym(g_Woh);
    __nv_bfloat16* Wol = (__nv_bfloat16*)sym(g_Wol);
    __nv_bfloat16* Qh  = (__nv_bfloat16*)sym(g_Qh);
    __nv_bfloat16* Ql  = (__nv_bfloat16*)sym(g_Ql);
    __nv_bfloat16* Kh  = (__nv_bfloat16*)sym(g_Kh);
    __nv_bfloat16* Kl  = (__nv_bfloat16*)sym(g_Kl);
    __nv_bfloat16* Vth = (__nv_bfloat16*)sym(g_Vth);
    __nv_bfloat16* Vtl = (__nv_bfloat16*)sym(g_Vtl);
    float*         S   = (float*)sym(g_S);
    __nv_bfloat16* Ph  = (__nv_bfloat16*)sym(g_Ph);
    __nv_bfloat16* Pl  = (__nv_bfloat16*)sym(g_Pl);
    __nv_bfloat16* Hh  = (__nv_bfloat16*)sym(g_Hh);
    __nv_bfloat16* Hl  = (__nv_bfloat16*)sym(g_Hl);

    cudaFuncSetAttribute(gemm_mma<0>, cudaFuncAttributeMaxDynamicSharedMemorySize, SMEM_TOTAL);
    cudaFuncSetAttribute(gemm_mma<1>, cudaFuncAttributeMaxDynamicSharedMemorySize, SMEM_TOTAL);
    cudaFuncSetAttribute(gemm_mma<2>, cudaFuncAttributeMaxDynamicSharedMemorySize, SMEM_TOTAL);
    cudaFuncSetAttribute(gemm_mma<3>, cudaFuncAttributeMaxDynamicSharedMemorySize, SMEM_TOTAL);

    // splits
    split_f32<<<(NTOK * CDIM / 4 + 255) / 256, 256>>>((const float4*)x, xh, xl, NTOK * CDIM / 4);
    split_f32<<<(CDIM * CDIM / 4 + 255) / 256, 256>>>((const float4*)Wq, Wqh, Wql, CDIM * CDIM / 4);
    split_f32<<<(CDIM * CDIM / 4 + 255) / 256, 256>>>((const float4*)Wk, Wkh, Wkl, CDIM * CDIM / 4);
    split_f32<<<(CDIM * CDIM / 4 + 255) / 256, 256>>>((const float4*)Wv, Wvh, Wvl, CDIM * CDIM / 4);
    split_f32<<<(CDIM * CDIM / 4 + 255) / 256, 256>>>((const float4*)Wo, Woh, Wol, CDIM * CDIM / 4);

    // QKV (fused over z): Q/K row-major, V scattered transposed
    GemmArgs a = {};
    a.Ahi = xh; a.Alo = xl;
    a.Bhi[0] = Wqh; a.Blo[0] = Wql; a.Bhi[1] = Wkh; a.Blo[1] = Wkl; a.Bhi[2] = Wvh; a.Blo[2] = Wvl;
    a.bias[0] = bq; a.bias[1] = bk; a.bias[2] = bv;
    a.Oh[0] = Qh; a.Ol[0] = Ql; a.Oh[1] = Kh; a.Ol[1] = Kl; a.Oh[2] = Vth; a.Ol[2] = Vtl;
    a.K = CDIM; a.Nout = CDIM;
    gemm_mma<0><<<dim3(CDIM / BN, NTOK / BM, 3), 256, SMEM_TOTAL>>>(a);

    // S = Q @ K^T  (fp32 out)
    GemmArgs as = {};
    as.Ahi = Qh; as.Alo = Ql; as.Bhi[0] = Kh; as.Blo[0] = Kl;
    as.Of = S; as.K = CDIM; as.Nout = NTOK;
    gemm_mma<1><<<dim3(NTOK / BN, NTOK / BM, 1), 256, SMEM_TOTAL>>>(as);

    // P = softmax(S) -> bf16 hi/lo
    softmax_rows<<<NTOK, 512>>>(S, Ph, Pl);

    // H = P @ V  (B = V^T, K-major over tokens)
    GemmArgs ap = {};
    ap.Ahi = Ph; ap.Alo = Pl; ap.Bhi[0] = Vth; ap.Blo[0] = Vtl;
    ap.Oh[0] = Hh; ap.Ol[0] = Hl; ap.K = NTOK; ap.Nout = CDIM;
    gemm_mma<2><<<dim3(CDIM / BN, NTOK / BM, 1), 256, SMEM_TOTAL>>>(ap);

    // out = x + H @ Wo^T + bo
    GemmArgs ao = {};
    ao.Ahi = Hh; ao.Alo = Hl; ao.Bhi[0] = Woh; ao.Blo[0] = Wol;
    ao.bias[0] = bo; ao.resid = x; ao.Of = out; ao.K = CDIM; ao.Nout = CDIM;
    gemm_mma<3><<<dim3(CDIM / BN, NTOK / BM, 1), 256, SMEM_TOTAL>>>(ao);
}

// round 6
// speedup vs baseline: 6.7547x; 2.6563x over previous
#include <cuda_runtime.h>
#include <cuda_fp16.h>
#include <math_constants.h>
#include <cstdint>

#define NTOK 4096
#define CDIM 1024
#define BM 128
#define BN 128
#define BK 32
#define LDS_A 40   // padded smem row stride (fp16 elems): 80B, conflict-free ldmatrix

// ---------------------------------------------------------------------------
// Scratch (__device__ globals; allocation-free rule)
// ---------------------------------------------------------------------------
__device__ __half g_xh[(size_t)NTOK * CDIM];
__device__ __half g_Wq[(size_t)CDIM * CDIM];
__device__ __half g_Wk[(size_t)CDIM * CDIM];
__device__ __half g_Wv[(size_t)CDIM * CDIM];
__device__ __half g_Wo[(size_t)CDIM * CDIM];
__device__ __half g_Q[(size_t)NTOK * CDIM];
__device__ __half g_K[(size_t)NTOK * CDIM];
__device__ __half g_Vt[(size_t)CDIM * NTOK];
__device__ float  g_S[(size_t)NTOK * NTOK];
__device__ __half g_P[(size_t)NTOK * NTOK];
__device__ __half g_H[(size_t)NTOK * CDIM];

// ---------------------------------------------------------------------------
// PTX helpers (sm_80-compatible only: cp.async / ldmatrix / mma.sync)
// ---------------------------------------------------------------------------
__device__ __forceinline__ uint32_t smem_u32(const void* p) {
    uint32_t a;
    asm("{ .reg .u64 t; cvta.to.shared.u64 t, %1; cvt.u32.u64 %0, t; }" : "=r"(a) : "l"(p));
    return a;
}

__device__ __forceinline__ void cpa16(uint32_t dst, const __half* src) {
    asm volatile("cp.async.cg.shared.global [%0], [%1], 16;" :: "r"(dst), "l"(src));
}
#define CP_COMMIT() asm volatile("cp.async.commit_group;")
#define CP_WAIT(n)  asm volatile("cp.async.wait_group %0;" :: "n"(n))

#define LDMX4(r, addr) \
    asm volatile("ldmatrix.sync.aligned.m8n8.x4.shared.b16 {%0,%1,%2,%3}, [%4];" \
                 : "=r"((r)[0]), "=r"((r)[1]), "=r"((r)[2]), "=r"((r)[3]) : "r"(addr))

__device__ __forceinline__ void mma16816(float* c, const uint32_t* a, const uint32_t* b) {
    asm volatile(
        "mma.sync.aligned.m16n8k16.row.col.f32.f16.f16.f32 "
        "{%0,%1,%2,%3}, {%4,%5,%6,%7}, {%8,%9}, {%0,%1,%2,%3};"
        : "+f"(c[0]), "+f"(c[1]), "+f"(c[2]), "+f"(c[3])
        : "r"(a[0]), "r"(a[1]), "r"(a[2]), "r"(a[3]), "r"(b[0]), "r"(b[1]));
}

// ---------------------------------------------------------------------------
// Generic fp16 mma.sync GEMM.  D[m][n] = sum_k A[m,k]*B[n,k]  (both K-major)
// MODE: 0=QKV (z selects W/b/out; z==2 scatters V^T), 1=S (fp32 out),
//       2=PV (fp16 out), 3=O (bias+resid, fp32 out)
// ---------------------------------------------------------------------------
struct GemmArgs {
    const __half* Ah;
    const __half* Bh[3];
    const float* bias[3];
    const float* resid;
    __half* Oh[3];
    float* Of;
    int K;     // reduction length
    int Nout;  // output row stride
};

// tile sizes in fp16 elems / bytes
#define TILE_E (BM * LDS_A)          // 5120 elems per 128x32 tile
#define TILE_B (TILE_E * 2)          // 10240 bytes
#define STAGE_B (2 * TILE_B)         // A, B   (20480)
#define NSTAGE 3
#define SMEM_TOTAL (NSTAGE * STAGE_B)  // 61440

__device__ __forceinline__ void load_tile_async(uint32_t sbase, const __half* __restrict__ g,
                                                int row0, int K, int kcol, int t) {
#pragma unroll
    for (int i = 0; i < 2; ++i) {
        int id = t + i * 256;
        int row = id >> 2, q = id & 3;
        cpa16(sbase + (uint32_t)(row * LDS_A + q * 8) * 2,
              g + (size_t)(row0 + row) * K + kcol + q * 8);
    }
}

template <int MODE>
__global__ __launch_bounds__(256, 2) void gemm_mma(const GemmArgs p) {
    extern __shared__ __half smem[];
    const uint32_t sb = smem_u32(smem);
    const int t = threadIdx.x;
    const int lane = t & 31;
    const int wid = t >> 5;
    const int m0 = blockIdx.y * BM;
    const int n0 = blockIdx.x * BN;
    const int z = (MODE == 0) ? blockIdx.z : 0;
    const __half* Bg = p.Bh[z];
    const int K = p.K;
    const int nch = K / BK;

    const int warp_m = (wid & 1) * 64;
    const int warp_n = (wid >> 1) * 32;

    // lane-resolved byte offsets within a tile for ldmatrix
    const uint32_t aoff = (uint32_t)((warp_m + (lane & 15)) * LDS_A + (lane >> 4) * 8) * 2;
    const uint32_t boff = (uint32_t)((warp_n + ((lane >> 4) & 1) * 8 + (lane & 7)) * LDS_A
                                     + ((lane >> 3) & 1) * 8) * 2;

    float acc[4][4][4];
#pragma unroll
    for (int i = 0; i < 4; ++i)
#pragma unroll
        for (int j = 0; j < 4; ++j)
#pragma unroll
            for (int r = 0; r < 4; ++r) acc[i][j][r] = 0.0f;

    // prologue: stages 0 and 1
#pragma unroll
    for (int s = 0; s < 2; ++s) {
        uint32_t sg = sb + s * STAGE_B;
        int kc = s * BK;
        load_tile_async(sg + 0 * TILE_B, p.Ah, m0, K, kc, t);
        load_tile_async(sg + 1 * TILE_B, Bg, n0, K, kc, t);
        CP_COMMIT();
    }

    int slot = 0;       // slot of chunk c  (c % 3)
    int slot2 = 2;      // slot of chunk c+2
    for (int c = 0; c < nch; ++c) {
        if (c + 1 < nch) { CP_WAIT(1); } else { CP_WAIT(0); }
        __syncthreads();

        if (c + 2 < nch) {
            uint32_t sg = sb + slot2 * STAGE_B;
            int kc = (c + 2) * BK;
            load_tile_async(sg + 0 * TILE_B, p.Ah, m0, K, kc, t);
            load_tile_async(sg + 1 * TILE_B, Bg, n0, K, kc, t);
            CP_COMMIT();
        }

        const uint32_t s0 = sb + slot * STAGE_B;
#pragma unroll
        for (int s = 0; s < 2; ++s) {
            uint32_t ah[4][4], bh[4][2];
#pragma unroll
            for (int i = 0; i < 4; ++i) {
                const uint32_t ao = (uint32_t)(i * 16 * LDS_A + s * 16) * 2;
                LDMX4(ah[i], s0 + 0 * TILE_B + aoff + ao);
            }
#pragma unroll
            for (int g = 0; g < 2; ++g) {
                const uint32_t bo = (uint32_t)(g * 16 * LDS_A + s * 16) * 2;
                uint32_t r[4];
                LDMX4(r, s0 + 1 * TILE_B + boff + bo);
                bh[2 * g][0] = r[0]; bh[2 * g][1] = r[1];
                bh[2 * g + 1][0] = r[2]; bh[2 * g + 1][1] = r[3];
            }
#pragma unroll
            for (int i = 0; i < 4; ++i)
#pragma unroll
                for (int j = 0; j < 4; ++j)
                    mma16816(acc[i][j], ah[i], bh[j]);
        }
        slot = (slot + 1 == NSTAGE) ? 0 : slot + 1;
        slot2 = (slot2 + 1 == NSTAGE) ? 0 : slot2 + 1;
    }

    // ------------------------------- epilogue ------------------------------
    const float* bias = (MODE == 0) ? p.bias[z] : ((MODE == 3) ? p.bias[0] : nullptr);

#pragma unroll
    for (int i = 0; i < 4; ++i) {
        const int r0 = m0 + warp_m + i * 16 + (lane >> 2);
        const int r1 = r0 + 8;
#pragma unroll
        for (int j = 0; j < 4; ++j) {
            const int cc = n0 + warp_n + j * 8 + (lane & 3) * 2;
            float v0 = acc[i][j][0], v1 = acc[i][j][1];
            float v2 = acc[i][j][2], v3 = acc[i][j][3];

            if (MODE == 1) {
                *(float2*)(p.Of + (size_t)r0 * p.Nout + cc) = make_float2(v0, v1);
                *(float2*)(p.Of + (size_t)r1 * p.Nout + cc) = make_float2(v2, v3);
            } else if (MODE == 3) {
                const float b0 = bias[cc], b1 = bias[cc + 1];
                const float* rs = p.resid;
                float2 ra = *(const float2*)(rs + (size_t)r0 * p.Nout + cc);
                float2 rb = *(const float2*)(rs + (size_t)r1 * p.Nout + cc);
                *(float2*)(p.Of + (size_t)r0 * p.Nout + cc) = make_float2(v0 + b0 + ra.x, v1 + b1 + ra.y);
                *(float2*)(p.Of + (size_t)r1 * p.Nout + cc) = make_float2(v2 + b0 + rb.x, v3 + b1 + rb.y);
            } else {
                if (MODE == 0) {
                    const float b0 = bias[cc], b1 = bias[cc + 1];
                    v0 += b0; v1 += b1; v2 += b0; v3 += b1;
                }
                __half h0 = __float2half_rn(v0), h1 = __float2half_rn(v1);
                __half h2 = __float2half_rn(v2), h3 = __float2half_rn(v3);
                if (MODE == 0 && z == 2) {
                    // scatter transposed: Vt[channel][token]
                    __half* oh = p.Oh[2];
                    oh[(size_t)cc * NTOK + r0] = h0;
                    oh[(size_t)(cc + 1) * NTOK + r0] = h1;
                    oh[(size_t)cc * NTOK + r1] = h2;
                    oh[(size_t)(cc + 1) * NTOK + r1] = h3;
                } else {
                    __half* oh = p.Oh[z];
                    *(__half2*)(oh + (size_t)r0 * p.Nout + cc) = __halves2half2(h0, h1);
                    *(__half2*)(oh + (size_t)r1 * p.Nout + cc) = __halves2half2(h2, h3);
                }
            }
        }
    }
}

// ---------------------------------------------------------------------------
// fp32 -> fp16 convert
// ---------------------------------------------------------------------------
__global__ __launch_bounds__(256) void tohalf(const float4* __restrict__ in,
                                              __half* __restrict__ out, int n4) {
    int i = blockIdx.x * 256 + threadIdx.x;
    if (i >= n4) return;
    float4 v = in[i];
    *(__half2*)(out + (size_t)i * 4)     = __floats2half2_rn(v.x, v.y);
    *(__half2*)(out + (size_t)i * 4 + 2) = __floats2half2_rn(v.z, v.w);
}

// ---------------------------------------------------------------------------
// Row softmax: S fp32 [4096] -> P fp16
// ---------------------------------------------------------------------------
__device__ __forceinline__ float warpMax(float v) {
#pragma unroll
    for (int o = 16; o > 0; o >>= 1) v = fmaxf(v, __shfl_xor_sync(0xffffffffu, v, o));
    return v;
}
__device__ __forceinline__ float warpSum(float v) {
#pragma unroll
    for (int o = 16; o > 0; o >>= 1) v += __shfl_xor_sync(0xffffffffu, v, o);
    return v;
}

__global__ __launch_bounds__(512) void softmax_rows(const float* __restrict__ S,
                                                    __half* __restrict__ P) {
    __shared__ float red[16];
    const int row = blockIdx.x;
    const float4* p = (const float4*)(S + (size_t)row * NTOK);
    const int t = threadIdx.x;

    float4 v0 = p[t];
    float4 v1 = p[t + 512];

    float m = fmaxf(fmaxf(fmaxf(v0.x, v0.y), fmaxf(v0.z, v0.w)),
                    fmaxf(fmaxf(v1.x, v1.y), fmaxf(v1.z, v1.w)));
    m = warpMax(m);
    if ((t & 31) == 0) red[t >> 5] = m;
    __syncthreads();
    if (t < 32) {
        float zz = (t < 16) ? red[t] : -CUDART_INF_F;
        zz = warpMax(zz);
        if (t == 0) red[0] = zz;
    }
    __syncthreads();
    m = red[0];
    __syncthreads();

    v0.x = __expf(v0.x - m); v0.y = __expf(v0.y - m);
    v0.z = __expf(v0.z - m); v0.w = __expf(v0.w - m);
    v1.x = __expf(v1.x - m); v1.y = __expf(v1.y - m);
    v1.z = __expf(v1.z - m); v1.w = __expf(v1.w - m);

    float s = (v0.x + v0.y + v0.z + v0.w) + (v1.x + v1.y + v1.z + v1.w);
    s = warpSum(s);
    if ((t & 31) == 0) red[t >> 5] = s;
    __syncthreads();
    if (t < 32) {
        float zz = (t < 16) ? red[t] : 0.0f;
        zz = warpSum(zz);
        if (t == 0) red[0] = zz;
    }
    __syncthreads();
    const float inv = 1.0f / red[0];

    size_t base = (size_t)row * NTOK;
    *(__half2*)(P + base + 4 * t)            = __floats2half2_rn(v0.x * inv, v0.y * inv);
    *(__half2*)(P + base + 4 * t + 2)        = __floats2half2_rn(v0.z * inv, v0.w * inv);
    *(__half2*)(P + base + 2048 + 4 * t)     = __floats2half2_rn(v1.x * inv, v1.y * inv);
    *(__half2*)(P + base + 2048 + 4 * t + 2) = __floats2half2_rn(v1.z * inv, v1.w * inv);
}

// ---------------------------------------------------------------------------
// Launch
// ---------------------------------------------------------------------------
static void* sym(const void* s) { void* p; cudaGetSymbolAddress(&p, s); return p; }

extern "C" void kernel_launch(void* const* d_in, const int* in_sizes, int n_in,
                              void* d_out, int out_size) {
    const float* x  = (const float*)d_in[0];
    const float* Wq = (const float*)d_in[1];
    const float* bq = (const float*)d_in[2];
    const float* Wk = (const float*)d_in[3];
    const float* bk = (const float*)d_in[4];
    const float* Wv = (const float*)d_in[5];
    const float* bv = (const float*)d_in[6];
    const float* Wo = (const float*)d_in[7];
    const float* bo = (const float*)d_in[8];
    float* out = (float*)d_out;

    __half* xh  = (__half*)sym(g_xh);
    __half* Wqh = (__half*)sym(g_Wq);
    __half* Wkh = (__half*)sym(g_Wk);
    __half* Wvh = (__half*)sym(g_Wv);
    __half* Woh = (__half*)sym(g_Wo);
    __half* Q   = (__half*)sym(g_Q);
    __half* K   = (__half*)sym(g_K);
    __half* Vt  = (__half*)sym(g_Vt);
    float*  S   = (float*)sym(g_S);
    __half* P   = (__half*)sym(g_P);
    __half* H   = (__half*)sym(g_H);

    cudaFuncSetAttribute(gemm_mma<0>, cudaFuncAttributeMaxDynamicSharedMemorySize, SMEM_TOTAL);
    cudaFuncSetAttribute(gemm_mma<1>, cudaFuncAttributeMaxDynamicSharedMemorySize, SMEM_TOTAL);
    cudaFuncSetAttribute(gemm_mma<2>, cudaFuncAttributeMaxDynamicSharedMemorySize, SMEM_TOTAL);
    cudaFuncSetAttribute(gemm_mma<3>, cudaFuncAttributeMaxDynamicSharedMemorySize, SMEM_TOTAL);

    // converts
    tohalf<<<(NTOK * CDIM / 4 + 255) / 256, 256>>>((const float4*)x, xh, NTOK * CDIM / 4);
    tohalf<<<(CDIM * CDIM / 4 + 255) / 256, 256>>>((const float4*)Wq, Wqh, CDIM * CDIM / 4);
    tohalf<<<(CDIM * CDIM / 4 + 255) / 256, 256>>>((const float4*)Wk, Wkh, CDIM * CDIM / 4);
    tohalf<<<(CDIM * CDIM / 4 + 255) / 256, 256>>>((const float4*)Wv, Wvh, CDIM * CDIM / 4);
    tohalf<<<(CDIM * CDIM / 4 + 255) / 256, 256>>>((const float4*)Wo, Woh, CDIM * CDIM / 4);

    // QKV (fused over z): Q/K row-major, V scattered transposed
    GemmArgs a = {};
    a.Ah = xh;
    a.Bh[0] = Wqh; a.Bh[1] = Wkh; a.Bh[2] = Wvh;
    a.bias[0] = bq; a.bias[1] = bk; a.bias[2] = bv;
    a.Oh[0] = Q; a.Oh[1] = K; a.Oh[2] = Vt;
    a.K = CDIM; a.Nout = CDIM;
    gemm_mma<0><<<dim3(CDIM / BN, NTOK / BM, 3), 256, SMEM_TOTAL>>>(a);

    // S = Q @ K^T  (fp32 out)
    GemmArgs as = {};
    as.Ah = Q; as.Bh[0] = K;
    as.Of = S; as.K = CDIM; as.Nout = NTOK;
    gemm_mma<1><<<dim3(NTOK / BN, NTOK / BM, 1), 256, SMEM_TOTAL>>>(as);

    // P = softmax(S) -> fp16
    softmax_rows<<<NTOK, 512>>>(S, P);

    // H = P @ V  (B = V^T, K-major over tokens)
    GemmArgs ap = {};
    ap.Ah = P; ap.Bh[0] = Vt;
    ap.Oh[0] = H; ap.K = NTOK; ap.Nout = CDIM;
    gemm_mma<2><<<dim3(CDIM / BN, NTOK / BM, 1), 256, SMEM_TOTAL>>>(ap);

    // out = x + H @ Wo^T + bo
    GemmArgs ao = {};
    ao.Ah = H; ao.Bh[0] = Woh;
    ao.bias[0] = bo; ao.resid = x; ao.Of = out; ao.K = CDIM; ao.Nout = CDIM;
    gemm_mma<3><<<dim3(CDIM / BN, NTOK / BM, 1), 256, SMEM_TOTAL>>>(ao);
}

// round 9
// speedup vs baseline: 6.9774x; 1.0330x over previous
#include <cuda_runtime.h>
#include <cuda_fp16.h>
#include <math_constants.h>
#include <cstdint>

#define NTOK 4096
#define CDIM 1024
#define BM 128
#define BN 128
#define BK 32
#define LDS_A 40    // A-tile row stride (fp16 elems): 80B, conflict-free ldmatrix
#define LDS_B 136   // trans-B tile row stride (fp16 elems): 272B, conflict-free ldmatrix.trans

// ---------------------------------------------------------------------------
// Scratch (__device__ globals; allocation-free rule)
// ---------------------------------------------------------------------------
__device__ __half g_xh[(size_t)NTOK * CDIM];
__device__ __half g_Wq[(size_t)CDIM * CDIM];
__device__ __half g_Wk[(size_t)CDIM * CDIM];
__device__ __half g_Wv[(size_t)CDIM * CDIM];
__device__ __half g_Wo[(size_t)CDIM * CDIM];
__device__ __half g_Q[(size_t)NTOK * CDIM];
__device__ __half g_K[(size_t)NTOK * CDIM];
__device__ __half g_V[(size_t)NTOK * CDIM];    // row-major (no transpose)
__device__ float  g_S[(size_t)NTOK * NTOK];
__device__ __half g_P[(size_t)NTOK * NTOK];
__device__ __half g_H[(size_t)NTOK * CDIM];

// ---------------------------------------------------------------------------
// PTX helpers (sm_80-compatible only: cp.async / ldmatrix / mma.sync)
// ---------------------------------------------------------------------------
__device__ __forceinline__ uint32_t smem_u32(const void* p) {
    uint32_t a;
    asm("{ .reg .u64 t; cvta.to.shared.u64 t, %1; cvt.u32.u64 %0, t; }" : "=r"(a) : "l"(p));
    return a;
}

__device__ __forceinline__ void cpa16(uint32_t dst, const __half* src) {
    asm volatile("cp.async.cg.shared.global [%0], [%1], 16;" :: "r"(dst), "l"(src));
}
#define CP_COMMIT() asm volatile("cp.async.commit_group;")
#define CP_WAIT(n)  asm volatile("cp.async.wait_group %0;" :: "n"(n))

#define LDMX4(r, addr) \
    asm volatile("ldmatrix.sync.aligned.m8n8.x4.shared.b16 {%0,%1,%2,%3}, [%4];" \
                 : "=r"((r)[0]), "=r"((r)[1]), "=r"((r)[2]), "=r"((r)[3]) : "r"(addr))

#define LDMX4T(r, addr) \
    asm volatile("ldmatrix.sync.aligned.m8n8.x4.trans.shared.b16 {%0,%1,%2,%3}, [%4];" \
                 : "=r"((r)[0]), "=r"((r)[1]), "=r"((r)[2]), "=r"((r)[3]) : "r"(addr))

__device__ __forceinline__ void mma16816(float* c, const uint32_t* a, const uint32_t* b) {
    asm volatile(
        "mma.sync.aligned.m16n8k16.row.col.f32.f16.f16.f32 "
        "{%0,%1,%2,%3}, {%4,%5,%6,%7}, {%8,%9}, {%0,%1,%2,%3};"
        : "+f"(c[0]), "+f"(c[1]), "+f"(c[2]), "+f"(c[3])
        : "r"(a[0]), "r"(a[1]), "r"(a[2]), "r"(a[3]), "r"(b[0]), "r"(b[1]));
}

// ---------------------------------------------------------------------------
// Generic fp16 mma.sync GEMM.
// MODE 0: QKV   D = x @ W^T + b   (B K-major [n][k]),   fp16 out (z selects)
// MODE 1: S     D = Q @ K^T       (B K-major),           fp32 out
// MODE 2: PV    D = P @ V         (B row-major [k][n] -> trans-B path), fp16 out
// MODE 3: O     D = H @ Wo^T + bo + resid (B K-major),   fp32 out
// ---------------------------------------------------------------------------
struct GemmArgs {
    const __half* Ah;
    const __half* Bh[3];
    const float* bias[3];
    const float* resid;
    __half* Oh[3];
    float* Of;
    int K;     // reduction length
    int Nout;  // output row stride
};

// tile sizes
#define TILE_E (BM * LDS_A)            // 5120 elems per 128x32 A-tile
#define TILE_B (TILE_E * 2)            // 10240 bytes
// trans-B tile: 32 rows (k) x 136 halves = 8704 bytes  (fits in the B slot)
#define STAGE_B (2 * TILE_B)           // A slot + B slot (20480)
#define NSTAGE 3
#define SMEM_TOTAL (NSTAGE * STAGE_B)  // 61440

// K-major tile loader: 128 rows x 32 k
__device__ __forceinline__ void load_tile_async(uint32_t sbase, const __half* __restrict__ g,
                                                int row0, int K, int kcol, int t) {
#pragma unroll
    for (int i = 0; i < 2; ++i) {
        int id = t + i * 256;
        int row = id >> 2, q = id & 3;
        cpa16(sbase + (uint32_t)(row * LDS_A + q * 8) * 2,
              g + (size_t)(row0 + row) * K + kcol + q * 8);
    }
}

// trans-B tile loader: 32 rows (k) x 128 halves (n), n contiguous
__device__ __forceinline__ void load_btile_trans(uint32_t sbase, const __half* __restrict__ g,
                                                 int n0, int kc, int t) {
#pragma unroll
    for (int i = 0; i < 2; ++i) {
        int id = t + i * 256;          // 0..511
        int row = id >> 4;             // 0..31 (k)
        int q = id & 15;               // 16B chunk within 256B row
        cpa16(sbase + (uint32_t)(row * LDS_B + q * 8) * 2,
              g + (size_t)(kc + row) * CDIM + n0 + q * 8);
    }
}

template <int MODE>
__global__ __launch_bounds__(256, 2) void gemm_mma(const GemmArgs p) {
    extern __shared__ __half smem[];
    const uint32_t sb = smem_u32(smem);
    const int t = threadIdx.x;
    const int lane = t & 31;
    const int wid = t >> 5;
    const int m0 = blockIdx.y * BM;
    const int n0 = blockIdx.x * BN;
    const int z = (MODE == 0) ? blockIdx.z : 0;
    const __half* Bg = p.Bh[z];
    const int K = p.K;
    const int nch = K / BK;

    const int warp_m = (wid & 1) * 64;
    const int warp_n = (wid >> 1) * 32;

    // lane-resolved byte offsets for ldmatrix
    const uint32_t aoff = (uint32_t)((warp_m + (lane & 15)) * LDS_A + (lane >> 4) * 8) * 2;
    const uint32_t boff = (uint32_t)((warp_n + ((lane >> 4) & 1) * 8 + (lane & 7)) * LDS_A
                                     + ((lane >> 3) & 1) * 8) * 2;
    // trans-B: lane -> (k_local, n_off); groups of 8 lanes = the four 8x8 tiles
    const uint32_t boffT = (uint32_t)(((((lane >> 3) & 1) * 8 + (lane & 7)) * LDS_B)
                                      + warp_n + (lane >> 4) * 8) * 2;

    float acc[4][4][4];
#pragma unroll
    for (int i = 0; i < 4; ++i)
#pragma unroll
        for (int j = 0; j < 4; ++j)
#pragma unroll
            for (int r = 0; r < 4; ++r) acc[i][j][r] = 0.0f;

    // prologue: stages 0 and 1
#pragma unroll
    for (int s = 0; s < 2; ++s) {
        uint32_t sg = sb + s * STAGE_B;
        int kc = s * BK;
        load_tile_async(sg + 0 * TILE_B, p.Ah, m0, K, kc, t);
        if (MODE == 2) load_btile_trans(sg + TILE_B, Bg, n0, kc, t);
        else           load_tile_async(sg + TILE_B, Bg, n0, K, kc, t);
        CP_COMMIT();
    }

    int slot = 0;
    int slot2 = 2;
    for (int c = 0; c < nch; ++c) {
        if (c + 1 < nch) { CP_WAIT(1); } else { CP_WAIT(0); }
        __syncthreads();

        if (c + 2 < nch) {
            uint32_t sg = sb + slot2 * STAGE_B;
            int kc = (c + 2) * BK;
            load_tile_async(sg + 0 * TILE_B, p.Ah, m0, K, kc, t);
            if (MODE == 2) load_btile_trans(sg + TILE_B, Bg, n0, kc, t);
            else           load_tile_async(sg + TILE_B, Bg, n0, K, kc, t);
            CP_COMMIT();
        }

        const uint32_t s0 = sb + slot * STAGE_B;
#pragma unroll
        for (int s = 0; s < 2; ++s) {
            uint32_t ah[4][4], bh[4][2];
#pragma unroll
            for (int i = 0; i < 4; ++i) {
                const uint32_t ao = (uint32_t)(i * 16 * LDS_A + s * 16) * 2;
                LDMX4(ah[i], s0 + 0 * TILE_B + aoff + ao);
            }
#pragma unroll
            for (int g = 0; g < 2; ++g) {
                uint32_t r[4];
                if (MODE == 2) {
                    const uint32_t bo = (uint32_t)(s * 16 * LDS_B + g * 16) * 2;
                    LDMX4T(r, s0 + TILE_B + boffT + bo);
                } else {
                    const uint32_t bo = (uint32_t)(g * 16 * LDS_A + s * 16) * 2;
                    LDMX4(r, s0 + TILE_B + boff + bo);
                }
                bh[2 * g][0] = r[0]; bh[2 * g][1] = r[1];
                bh[2 * g + 1][0] = r[2]; bh[2 * g + 1][1] = r[3];
            }
#pragma unroll
            for (int i = 0; i < 4; ++i)
#pragma unroll
                for (int j = 0; j < 4; ++j)
                    mma16816(acc[i][j], ah[i], bh[j]);
        }
        slot = (slot + 1 == NSTAGE) ? 0 : slot + 1;
        slot2 = (slot2 + 1 == NSTAGE) ? 0 : slot2 + 1;
    }

    // ------------------------------- epilogue ------------------------------
    const float* bias = (MODE == 0) ? p.bias[z] : ((MODE == 3) ? p.bias[0] : nullptr);

#pragma unroll
    for (int i = 0; i < 4; ++i) {
        const int r0 = m0 + warp_m + i * 16 + (lane >> 2);
        const int r1 = r0 + 8;
#pragma unroll
        for (int j = 0; j < 4; ++j) {
            const int cc = n0 + warp_n + j * 8 + (lane & 3) * 2;
            float v0 = acc[i][j][0], v1 = acc[i][j][1];
            float v2 = acc[i][j][2], v3 = acc[i][j][3];

            if (MODE == 1) {
                *(float2*)(p.Of + (size_t)r0 * p.Nout + cc) = make_float2(v0, v1);
                *(float2*)(p.Of + (size_t)r1 * p.Nout + cc) = make_float2(v2, v3);
            } else if (MODE == 3) {
                const float b0 = bias[cc], b1 = bias[cc + 1];
                const float* rs = p.resid;
                float2 ra = *(const float2*)(rs + (size_t)r0 * p.Nout + cc);
                float2 rb = *(const float2*)(rs + (size_t)r1 * p.Nout + cc);
                *(float2*)(p.Of + (size_t)r0 * p.Nout + cc) = make_float2(v0 + b0 + ra.x, v1 + b1 + ra.y);
                *(float2*)(p.Of + (size_t)r1 * p.Nout + cc) = make_float2(v2 + b0 + rb.x, v3 + b1 + rb.y);
            } else {
                if (MODE == 0) {
                    const float b0 = bias[cc], b1 = bias[cc + 1];
                    v0 += b0; v1 += b1; v2 += b0; v3 += b1;
                }
                __half* oh = p.Oh[z];
                *(__half2*)(oh + (size_t)r0 * p.Nout + cc) =
                    __halves2half2(__float2half_rn(v0), __float2half_rn(v1));
                *(__half2*)(oh + (size_t)r1 * p.Nout + cc) =
                    __halves2half2(__float2half_rn(v2), __float2half_rn(v3));
            }
        }
    }
}

// ---------------------------------------------------------------------------
// Fused fp32 -> fp16 convert for x + 4 weights (one launch)
// ---------------------------------------------------------------------------
#define XN4 (NTOK * CDIM / 4)      // 1048576 float4
#define WN4 (CDIM * CDIM / 4)      // 262144 float4

__global__ __launch_bounds__(256) void tohalf_all(
    const float4* __restrict__ x,  __half* __restrict__ xh,
    const float4* __restrict__ w0, __half* __restrict__ o0,
    const float4* __restrict__ w1, __half* __restrict__ o1,
    const float4* __restrict__ w2, __half* __restrict__ o2,
    const float4* __restrict__ w3, __half* __restrict__ o3) {
    int i = blockIdx.x * 256 + threadIdx.x;
    const float4* in;
    __half* out;
    int k;
    if (i < XN4) { in = x; out = xh; k = i; }
    else {
        int j = i - XN4;
        int w = j >> 18;           // / WN4
        k = j & (WN4 - 1);
        switch (w) {
            case 0: in = w0; out = o0; break;
            case 1: in = w1; out = o1; break;
            case 2: in = w2; out = o2; break;
            default: in = w3; out = o3; break;
        }
    }
    float4 v = in[k];
    *(__half2*)(out + (size_t)k * 4)     = __floats2half2_rn(v.x, v.y);
    *(__half2*)(out + (size_t)k * 4 + 2) = __floats2half2_rn(v.z, v.w);
}

// ---------------------------------------------------------------------------
// Row softmax: S fp32 [4096] -> P fp16
// ---------------------------------------------------------------------------
__device__ __forceinline__ float warpMax(float v) {
#pragma unroll
    for (int o = 16; o > 0; o >>= 1) v = fmaxf(v, __shfl_xor_sync(0xffffffffu, v, o));
    return v;
}
__device__ __forceinline__ float warpSum(float v) {
#pragma unroll
    for (int o = 16; o > 0; o >>= 1) v += __shfl_xor_sync(0xffffffffu, v, o);
    return v;
}

__global__ __launch_bounds__(512) void softmax_rows(const float* __restrict__ S,
                                                    __half* __restrict__ P) {
    __shared__ float red[16];
    const int row = blockIdx.x;
    const float4* p = (const float4*)(S + (size_t)row * NTOK);
    const int t = threadIdx.x;

    float4 v0 = p[t];
    float4 v1 = p[t + 512];

    float m = fmaxf(fmaxf(fmaxf(v0.x, v0.y), fmaxf(v0.z, v0.w)),
                    fmaxf(fmaxf(v1.x, v1.y), fmaxf(v1.z, v1.w)));
    m = warpMax(m);
    if ((t & 31) == 0) red[t >> 5] = m;
    __syncthreads();
    if (t < 32) {
        float zz = (t < 16) ? red[t] : -CUDART_INF_F;
        zz = warpMax(zz);
        if (t == 0) red[0] = zz;
    }
    __syncthreads();
    m = red[0];
    __syncthreads();

    v0.x = __expf(v0.x - m); v0.y = __expf(v0.y - m);
    v0.z = __expf(v0.z - m); v0.w = __expf(v0.w - m);
    v1.x = __expf(v1.x - m); v1.y = __expf(v1.y - m);
    v1.z = __expf(v1.z - m); v1.w = __expf(v1.w - m);

    float s = (v0.x + v0.y + v0.z + v0.w) + (v1.x + v1.y + v1.z + v1.w);
    s = warpSum(s);
    if ((t & 31) == 0) red[t >> 5] = s;
    __syncthreads();
    if (t < 32) {
        float zz = (t < 16) ? red[t] : 0.0f;
        zz = warpSum(zz);
        if (t == 0) red[0] = zz;
    }
    __syncthreads();
    const float inv = 1.0f / red[0];

    size_t base = (size_t)row * NTOK;
    *(__half2*)(P + base + 4 * t)            = __floats2half2_rn(v0.x * inv, v0.y * inv);
    *(__half2*)(P + base + 4 * t + 2)        = __floats2half2_rn(v0.z * inv, v0.w * inv);
    *(__half2*)(P + base + 2048 + 4 * t)     = __floats2half2_rn(v1.x * inv, v1.y * inv);
    *(__half2*)(P + base + 2048 + 4 * t + 2) = __floats2half2_rn(v1.z * inv, v1.w * inv);
}

// ---------------------------------------------------------------------------
// Launch
// ---------------------------------------------------------------------------
static void* sym(const void* s) { void* p; cudaGetSymbolAddress(&p, s); return p; }

extern "C" void kernel_launch(void* const* d_in, const int* in_sizes, int n_in,
                              void* d_out, int out_size) {
    const float* x  = (const float*)d_in[0];
    const float* Wq = (const float*)d_in[1];
    const float* bq = (const float*)d_in[2];
    const float* Wk = (const float*)d_in[3];
    const float* bk = (const float*)d_in[4];
    const float* Wv = (const float*)d_in[5];
    const float* bv = (const float*)d_in[6];
    const float* Wo = (const float*)d_in[7];
    const float* bo = (const float*)d_in[8];
    float* out = (float*)d_out;

    __half* xh  = (__half*)sym(g_xh);
    __half* Wqh = (__half*)sym(g_Wq);
    __half* Wkh = (__half*)sym(g_Wk);
    __half* Wvh = (__half*)sym(g_Wv);
    __half* Woh = (__half*)sym(g_Wo);
    __half* Q   = (__half*)sym(g_Q);
    __half* K   = (__half*)sym(g_K);
    __half* V   = (__half*)sym(g_V);
    float*  S   = (float*)sym(g_S);
    __half* P   = (__half*)sym(g_P);
    __half* H   = (__half*)sym(g_H);

    cudaFuncSetAttribute(gemm_mma<0>, cudaFuncAttributeMaxDynamicSharedMemorySize, SMEM_TOTAL);
    cudaFuncSetAttribute(gemm_mma<1>, cudaFuncAttributeMaxDynamicSharedMemorySize, SMEM_TOTAL);
    cudaFuncSetAttribute(gemm_mma<2>, cudaFuncAttributeMaxDynamicSharedMemorySize, SMEM_TOTAL);
    cudaFuncSetAttribute(gemm_mma<3>, cudaFuncAttributeMaxDynamicSharedMemorySize, SMEM_TOTAL);

    // single fused convert
    tohalf_all<<<(XN4 + 4 * WN4) / 256, 256>>>(
        (const float4*)x, xh, (const float4*)Wq, Wqh, (const float4*)Wk, Wkh,
        (const float4*)Wv, Wvh, (const float4*)Wo, Woh);

    // QKV (fused over z): all outputs row-major now
    GemmArgs a = {};
    a.Ah = xh;
    a.Bh[0] = Wqh; a.Bh[1] = Wkh; a.Bh[2] = Wvh;
    a.bias[0] = bq; a.bias[1] = bk; a.bias[2] = bv;
    a.Oh[0] = Q; a.Oh[1] = K; a.Oh[2] = V;
    a.K = CDIM; a.Nout = CDIM;
    gemm_mma<0><<<dim3(CDIM / BN, NTOK / BM, 3), 256, SMEM_TOTAL>>>(a);

    // S = Q @ K^T  (fp32 out)
    GemmArgs as = {};
    as.Ah = Q; as.Bh[0] = K;
    as.Of = S; as.K = CDIM; as.Nout = NTOK;
    gemm_mma<1><<<dim3(NTOK / BN, NTOK / BM, 1), 256, SMEM_TOTAL>>>(as);

    // P = softmax(S) -> fp16
    softmax_rows<<<NTOK, 512>>>(S, P);

    // H = P @ V  (trans-B path: V row-major [token][channel])
    GemmArgs ap = {};
    ap.Ah = P; ap.Bh[0] = V;
    ap.Oh[0] = H; ap.K = NTOK; ap.Nout = CDIM;
    gemm_mma<2><<<dim3(CDIM / BN, NTOK / BM, 1), 256, SMEM_TOTAL>>>(ap);

    // out = x + H @ Wo^T + bo
    GemmArgs ao = {};
    ao.Ah = H; ao.Bh[0] = Woh;
    ao.bias[0] = bo; ao.resid = x; ao.Of = out; ao.K = CDIM; ao.Nout = CDIM;
    gemm_mma<3><<<dim3(CDIM / BN, NTOK / BM, 1), 256, SMEM_TOTAL>>>(ao);
}

// round 11
// speedup vs baseline: 7.2604x; 1.0406x over previous
#include <cuda_runtime.h>
#include <cuda_fp16.h>
#include <math_constants.h>
#include <cstdint>

#define NTOK 4096
#define CDIM 1024
#define BM 128
#define BN 128
#define BK 32
#define LDS_A 40    // K-major tile row stride (fp16 elems): 80B, conflict-free ldmatrix
#define LDS_B 136   // trans-B tile row stride (fp16 elems): 272B, conflict-free ldmatrix.trans

// ---------------------------------------------------------------------------
// Scratch (__device__ globals; allocation-free rule)
// ---------------------------------------------------------------------------
__device__ __half g_xh[(size_t)NTOK * CDIM];
__device__ __half g_Wq[(size_t)CDIM * CDIM];
__device__ __half g_Wk[(size_t)CDIM * CDIM];
__device__ __half g_Wv[(size_t)CDIM * CDIM];
__device__ __half g_Wo[(size_t)CDIM * CDIM];
__device__ __half g_Q[(size_t)NTOK * CDIM];
__device__ __half g_K[(size_t)NTOK * CDIM];
__device__ __half g_V[(size_t)NTOK * CDIM];
__device__ float  g_S[(size_t)NTOK * NTOK];
__device__ __half g_P[(size_t)NTOK * NTOK];
__device__ float  g_Hp[4ULL * NTOK * CDIM];   // PV split-K partials (fp32)
__device__ __half g_H[(size_t)NTOK * CDIM];

// dependency counters (reset by the convert kernel each call)
__device__ int g_cnt[256];
#define C_QDONE 0     // per Q m-block (8 tiles each)
#define C_KDONE 32    // per K m-block (8 tiles each)
#define C_SCNT  64    // per S m-block (32 n-tiles each)
#define C_PDONE 96    // per m-block softmax chunks (8 each)
#define C_HRDY  128   // per m-block PV tiles (8 nb x 4 ks = 32)
#define C_RDONE 160   // per m-block reduce chunks (8 each)
#define C_VALL  192   // V proj tiles (256 total)

// ---------------------------------------------------------------------------
// PTX helpers (sm_80-compatible only: cp.async / ldmatrix / mma.sync)
// ---------------------------------------------------------------------------
__device__ __forceinline__ uint32_t smem_u32(const void* p) {
    uint32_t a;
    asm("{ .reg .u64 t; cvta.to.shared.u64 t, %1; cvt.u32.u64 %0, t; }" : "=r"(a) : "l"(p));
    return a;
}

__device__ __forceinline__ void cpa16(uint32_t dst, const __half* src) {
    asm volatile("cp.async.cg.shared.global [%0], [%1], 16;" :: "r"(dst), "l"(src));
}
#define CP_COMMIT() asm volatile("cp.async.commit_group;")
#define CP_WAIT(n)  asm volatile("cp.async.wait_group %0;" :: "n"(n))

#define LDMX4(r, addr) \
    asm volatile("ldmatrix.sync.aligned.m8n8.x4.shared.b16 {%0,%1,%2,%3}, [%4];" \
                 : "=r"((r)[0]), "=r"((r)[1]), "=r"((r)[2]), "=r"((r)[3]) : "r"(addr))

#define LDMX4T(r, addr) \
    asm volatile("ldmatrix.sync.aligned.m8n8.x4.trans.shared.b16 {%0,%1,%2,%3}, [%4];" \
                 : "=r"((r)[0]), "=r"((r)[1]), "=r"((r)[2]), "=r"((r)[3]) : "r"(addr))

__device__ __forceinline__ void mma16816(float* c, const uint32_t* a, const uint32_t* b) {
    asm volatile(
        "mma.sync.aligned.m16n8k16.row.col.f32.f16.f16.f32 "
        "{%0,%1,%2,%3}, {%4,%5,%6,%7}, {%8,%9}, {%0,%1,%2,%3};"
        : "+f"(c[0]), "+f"(c[1]), "+f"(c[2]), "+f"(c[3])
        : "r"(a[0]), "r"(a[1]), "r"(a[2]), "r"(a[3]), "r"(b[0]), "r"(b[1]));
}

// ---------------------------------------------------------------------------
// sync helpers for the in-kernel DAG
// ---------------------------------------------------------------------------
__device__ __forceinline__ void spin_ge(int idx, int target) {
    volatile int* p = (volatile int*)&g_cnt[idx];
    if (threadIdx.x == 0) {
        while (*p < target) __nanosleep(128);
    }
    __syncthreads();
}
__device__ __forceinline__ void signal(int idx) {
    __threadfence();
    __syncthreads();
    if (threadIdx.x == 0) atomicAdd(&g_cnt[idx], 1);
}

// ---------------------------------------------------------------------------
// smem layout
// ---------------------------------------------------------------------------
#define TILE_E (BM * LDS_A)            // 5120 elems per 128x32 K-major tile
#define TILE_B (TILE_E * 2)            // 10240 bytes
#define STAGE_B (2 * TILE_B)           // A slot + B slot (20480)
#define NSTAGE 3
#define SMEM_TOTAL (NSTAGE * STAGE_B)  // 61440

// K-major tile loader: 128 rows x 32 k  (works for A and K-major B)
__device__ __forceinline__ void load_km(uint32_t sbase, const __half* __restrict__ g,
                                        int row0, int stride, int kcol, int t) {
#pragma unroll
    for (int i = 0; i < 2; ++i) {
        int id = t + i * 256;
        int row = id >> 2, q = id & 3;
        cpa16(sbase + (uint32_t)(row * LDS_A + q * 8) * 2,
              g + (size_t)(row0 + row) * stride + kcol + q * 8);
    }
}

// trans-B tile loader: 32 rows (k) x 128 halves (n), n contiguous (stride CDIM)
__device__ __forceinline__ void load_bt(uint32_t sbase, const __half* __restrict__ g,
                                        int n0, int kc, int t) {
#pragma unroll
    for (int i = 0; i < 2; ++i) {
        int id = t + i * 256;
        int row = id >> 4;
        int q = id & 15;
        cpa16(sbase + (uint32_t)(row * LDS_B + q * 8) * 2,
              g + (size_t)(kc + row) * CDIM + n0 + q * 8);
    }
}

// ---------------------------------------------------------------------------
// GEMM tile body: D[128,128] = A[m0.., :Klen] @ B^T  (A K-major; B K-major or trans)
// BT: 0 = B K-major [n][k], 1 = B row-major [k][n] via ldmatrix.trans
// EPI: 0 = fp16 out + bias, 1 = fp32 out, 2 = fp32 out + bias + resid
// ---------------------------------------------------------------------------
template <int BT, int EPI>
__device__ __forceinline__ void gemm_body(
    const __half* __restrict__ Ah, const __half* __restrict__ Bg,
    const float* __restrict__ bias, const float* __restrict__ resid,
    __half* __restrict__ oh, float* __restrict__ of,
    int Klen, int Astride, int Bstride, int Nout, int m0, int n0, uint32_t sb)
{
    const int t = threadIdx.x;
    const int lane = t & 31;
    const int wid = t >> 5;
    const int nch = Klen / BK;

    const int warp_m = (wid & 1) * 64;
    const int warp_n = (wid >> 1) * 32;

    const uint32_t aoff = (uint32_t)((warp_m + (lane & 15)) * LDS_A + (lane >> 4) * 8) * 2;
    const uint32_t boff = (uint32_t)((warp_n + ((lane >> 4) & 1) * 8 + (lane & 7)) * LDS_A
                                     + ((lane >> 3) & 1) * 8) * 2;
    const uint32_t boffT = (uint32_t)(((((lane >> 3) & 1) * 8 + (lane & 7)) * LDS_B)
                                      + warp_n + (lane >> 4) * 8) * 2;

    float acc[4][4][4];
#pragma unroll
    for (int i = 0; i < 4; ++i)
#pragma unroll
        for (int j = 0; j < 4; ++j)
#pragma unroll
            for (int r = 0; r < 4; ++r) acc[i][j][r] = 0.0f;

#pragma unroll
    for (int s = 0; s < 2; ++s) {
        uint32_t sg = sb + s * STAGE_B;
        int kc = s * BK;
        load_km(sg + 0 * TILE_B, Ah, m0, Astride, kc, t);
        if (BT) load_bt(sg + TILE_B, Bg, n0, kc, t);
        else    load_km(sg + TILE_B, Bg, n0, Bstride, kc, t);
        CP_COMMIT();
    }

    int slot = 0, slot2 = 2;
    for (int c = 0; c < nch; ++c) {
        if (c + 1 < nch) { CP_WAIT(1); } else { CP_WAIT(0); }
        __syncthreads();

        if (c + 2 < nch) {
            uint32_t sg = sb + slot2 * STAGE_B;
            int kc = (c + 2) * BK;
            load_km(sg + 0 * TILE_B, Ah, m0, Astride, kc, t);
            if (BT) load_bt(sg + TILE_B, Bg, n0, kc, t);
            else    load_km(sg + TILE_B, Bg, n0, Bstride, kc, t);
            CP_COMMIT();
        }

        const uint32_t s0 = sb + slot * STAGE_B;
#pragma unroll
        for (int s = 0; s < 2; ++s) {
            uint32_t ah[4][4], bh[4][2];
#pragma unroll
            for (int i = 0; i < 4; ++i) {
                const uint32_t ao = (uint32_t)(i * 16 * LDS_A + s * 16) * 2;
                LDMX4(ah[i], s0 + 0 * TILE_B + aoff + ao);
            }
#pragma unroll
            for (int g = 0; g < 2; ++g) {
                uint32_t r[4];
                if (BT) {
                    const uint32_t bo = (uint32_t)(s * 16 * LDS_B + g * 16) * 2;
                    LDMX4T(r, s0 + TILE_B + boffT + bo);
                } else {
                    const uint32_t bo = (uint32_t)(g * 16 * LDS_A + s * 16) * 2;
                    LDMX4(r, s0 + TILE_B + boff + bo);
                }
                bh[2 * g][0] = r[0]; bh[2 * g][1] = r[1];
                bh[2 * g + 1][0] = r[2]; bh[2 * g + 1][1] = r[3];
            }
#pragma unroll
            for (int i = 0; i < 4; ++i)
#pragma unroll
                for (int j = 0; j < 4; ++j)
                    mma16816(acc[i][j], ah[i], bh[j]);
        }
        slot = (slot + 1 == NSTAGE) ? 0 : slot + 1;
        slot2 = (slot2 + 1 == NSTAGE) ? 0 : slot2 + 1;
    }

    // epilogue
#pragma unroll
    for (int i = 0; i < 4; ++i) {
        const int r0 = m0 + warp_m + i * 16 + (lane >> 2);
        const int r1 = r0 + 8;
#pragma unroll
        for (int j = 0; j < 4; ++j) {
            const int cc = n0 + warp_n + j * 8 + (lane & 3) * 2;
            float v0 = acc[i][j][0], v1 = acc[i][j][1];
            float v2 = acc[i][j][2], v3 = acc[i][j][3];

            if (EPI == 1) {
                *(float2*)(of + (size_t)r0 * Nout + cc) = make_float2(v0, v1);
                *(float2*)(of + (size_t)r1 * Nout + cc) = make_float2(v2, v3);
            } else if (EPI == 2) {
                const float b0 = bias[cc], b1 = bias[cc + 1];
                float2 ra = *(const float2*)(resid + (size_t)r0 * Nout + cc);
                float2 rb = *(const float2*)(resid + (size_t)r1 * Nout + cc);
                *(float2*)(of + (size_t)r0 * Nout + cc) = make_float2(v0 + b0 + ra.x, v1 + b1 + ra.y);
                *(float2*)(of + (size_t)r1 * Nout + cc) = make_float2(v2 + b0 + rb.x, v3 + b1 + rb.y);
            } else {
                const float b0 = bias[cc], b1 = bias[cc + 1];
                v0 += b0; v1 += b1; v2 += b0; v3 += b1;
                *(__half2*)(oh + (size_t)r0 * Nout + cc) =
                    __halves2half2(__float2half_rn(v0), __float2half_rn(v1));
                *(__half2*)(oh + (size_t)r1 * Nout + cc) =
                    __halves2half2(__float2half_rn(v2), __float2half_rn(v3));
            }
        }
    }
}

// ---------------------------------------------------------------------------
// softmax body: 16 rows, 256 threads, fp32 S -> fp16 P
// ---------------------------------------------------------------------------
__device__ __forceinline__ float warpMax(float v) {
#pragma unroll
    for (int o = 16; o > 0; o >>= 1) v = fmaxf(v, __shfl_xor_sync(0xffffffffu, v, o));
    return v;
}
__device__ __forceinline__ float warpSum(float v) {
#pragma unroll
    for (int o = 16; o > 0; o >>= 1) v += __shfl_xor_sync(0xffffffffu, v, o);
    return v;
}

__device__ void softmax_body(const float* __restrict__ S, __half* __restrict__ P,
                             int row0, char* smemraw) {
    float* red = (float*)smemraw;
    const int t = threadIdx.x;
    const int lane = t & 31, wid = t >> 5;

    for (int r = 0; r < 16; ++r) {
        const int row = row0 + r;
        const float4* pr = (const float4*)(S + (size_t)row * NTOK);
        float4 v[4];
#pragma unroll
        for (int i = 0; i < 4; ++i) v[i] = pr[t + 256 * i];

        float m = -CUDART_INF_F;
#pragma unroll
        for (int i = 0; i < 4; ++i)
            m = fmaxf(m, fmaxf(fmaxf(v[i].x, v[i].y), fmaxf(v[i].z, v[i].w)));
        m = warpMax(m);
        if (lane == 0) red[wid] = m;
        __syncthreads();
        if (t < 32) {
            float z = (t < 8) ? red[t] : -CUDART_INF_F;
            z = warpMax(z);
            if (t == 0) red[8] = z;
        }
        __syncthreads();
        m = red[8];

        float s = 0.0f;
#pragma unroll
        for (int i = 0; i < 4; ++i) {
            v[i].x = __expf(v[i].x - m); v[i].y = __expf(v[i].y - m);
            v[i].z = __expf(v[i].z - m); v[i].w = __expf(v[i].w - m);
            s += (v[i].x + v[i].y) + (v[i].z + v[i].w);
        }
        s = warpSum(s);
        __syncthreads();
        if (lane == 0) red[wid] = s;
        __syncthreads();
        if (t < 32) {
            float z = (t < 8) ? red[t] : 0.0f;
            z = warpSum(z);
            if (t == 0) red[8] = z;
        }
        __syncthreads();
        const float inv = 1.0f / red[8];

        uint2* po = (uint2*)(P + (size_t)row * NTOK);
#pragma unroll
        for (int i = 0; i < 4; ++i) {
            __half2 h0 = __floats2half2_rn(v[i].x * inv, v[i].y * inv);
            __half2 h1 = __floats2half2_rn(v[i].z * inv, v[i].w * inv);
            uint2 u;
            u.x = *(uint32_t*)&h0;
            u.y = *(uint32_t*)&h1;
            po[t + 256 * i] = u;
        }
        __syncthreads();
    }
}

// ---------------------------------------------------------------------------
// H reduce body: H = sum of 4 fp32 partials -> fp16.  16 rows, 256 threads.
// ---------------------------------------------------------------------------
__device__ void reduce_body(const float* __restrict__ Hp, __half* __restrict__ H, int row0) {
    const int t = threadIdx.x;
    const size_t plane = (size_t)NTOK * CDIM;
    for (int r = 0; r < 16; ++r) {
        const int row = row0 + r;
        const float4* h0 = (const float4*)(Hp + (size_t)row * CDIM);
        const float4* h1 = (const float4*)(Hp + plane + (size_t)row * CDIM);
        const float4* h2 = (const float4*)(Hp + 2 * plane + (size_t)row * CDIM);
        const float4* h3 = (const float4*)(Hp + 3 * plane + (size_t)row * CDIM);
        float4 a = h0[t], b = h1[t], c = h2[t], d = h3[t];
        __half2 p0 = __floats2half2_rn(a.x + b.x + c.x + d.x, a.y + b.y + c.y + d.y);
        __half2 p1 = __floats2half2_rn(a.z + b.z + c.z + d.z, a.w + b.w + c.w + d.w);
        uint2 u;
        u.x = *(uint32_t*)&p0;
        u.y = *(uint32_t*)&p1;
        ((uint2*)(H + (size_t)row * CDIM))[t] = u;
    }
}

// ---------------------------------------------------------------------------
// Mega kernel: whole post-convert DAG in one launch, ordered producer->consumer.
// Roles by blockIdx.x:
//  [0,256)     Kproj   [256,512) Qproj   [512,768) Vproj
//  [768,1792)  S       [1792,2048) softmax
//  [2048,3072) PV (split-K x4, fp32 partials)
//  [3072,3328) H reduce
//  [3328,3584) O
// ---------------------------------------------------------------------------
struct MegaArgs {
    const float *x, *bq, *bk, *bv, *bo;
    float* out;
};
#define MEGA_GRID 3584

__global__ __launch_bounds__(256, 2) void mega(const MegaArgs a) {
    extern __shared__ char smem[];
    const uint32_t sb = smem_u32(smem);
    const int b = blockIdx.x;

    if (b < 256) {                       // K projection
        const int kb = b >> 3, nb = b & 7;
        gemm_body<0, 0>(g_xh, g_Wk, a.bk, nullptr, g_K, nullptr,
                        CDIM, CDIM, CDIM, CDIM, kb * 128, nb * 128, sb);
        signal(C_KDONE + kb);
    } else if (b < 512) {                // Q projection
        const int i = b - 256, qb = i >> 3, nb = i & 7;
        gemm_body<0, 0>(g_xh, g_Wq, a.bq, nullptr, g_Q, nullptr,
                        CDIM, CDIM, CDIM, CDIM, qb * 128, nb * 128, sb);
        signal(C_QDONE + qb);
    } else if (b < 768) {                // V projection
        const int i = b - 512, vb = i >> 3, nb = i & 7;
        gemm_body<0, 0>(g_xh, g_Wv, a.bv, nullptr, g_V, nullptr,
                        CDIM, CDIM, CDIM, CDIM, vb * 128, nb * 128, sb);
        signal(C_VALL);
    } else if (b < 1792) {               // S = Q @ K^T (fp32)
        const int i = b - 768, mb = i >> 5, nb = i & 31;
        spin_ge(C_QDONE + mb, 8);
        spin_ge(C_KDONE + nb, 8);
        gemm_body<0, 1>(g_Q, g_K, nullptr, nullptr, nullptr, g_S,
                        CDIM, CDIM, CDIM, NTOK, mb * 128, nb * 128, sb);
        signal(C_SCNT + mb);
    } else if (b < 2048) {               // softmax
        const int i = b - 1792, mb = i >> 3, rq = i & 7;
        spin_ge(C_SCNT + mb, 32);
        softmax_body(g_S, g_P, mb * 128 + rq * 16, smem);
        signal(C_PDONE + mb);
    } else if (b < 3072) {               // PV split-K partial
        const int i = b - 2048, mb = i >> 5, r = i & 31;
        const int nb = r >> 2, ks = r & 3;
        spin_ge(C_PDONE + mb, 8);
        spin_ge(C_VALL, 256);
        gemm_body<1, 1>(g_P + ks * 1024, g_V + (size_t)ks * 1024 * CDIM,
                        nullptr, nullptr, nullptr, g_Hp + (size_t)ks * NTOK * CDIM,
                        1024, NTOK, 0, CDIM, mb * 128, nb * 128, sb);
        signal(C_HRDY + mb);
    } else if (b < 3328) {               // H reduce
        const int i = b - 3072, mb = i >> 3, rq = i & 7;
        spin_ge(C_HRDY + mb, 32);
        reduce_body(g_Hp, g_H, mb * 128 + rq * 16);
        signal(C_RDONE + mb);
    } else {                             // O = x + H @ Wo^T + bo
        const int i = b - 3328, mb = i >> 3, nb = i & 7;
        spin_ge(C_RDONE + mb, 8);
        gemm_body<0, 2>(g_H, g_Wo, a.bo, a.x, nullptr, a.out,
                        CDIM, CDIM, CDIM, CDIM, mb * 128, nb * 128, sb);
    }
}

// ---------------------------------------------------------------------------
// Fused fp32 -> fp16 convert for x + 4 weights, and counter reset (one launch)
// ---------------------------------------------------------------------------
#define XN4 (NTOK * CDIM / 4)      // 1048576 float4
#define WN4 (CDIM * CDIM / 4)      // 262144 float4

__global__ __launch_bounds__(256) void tohalf_all(
    const float4* __restrict__ x,  __half* __restrict__ xh,
    const float4* __restrict__ w0, __half* __restrict__ o0,
    const float4* __restrict__ w1, __half* __restrict__ o1,
    const float4* __restrict__ w2, __half* __restrict__ o2,
    const float4* __restrict__ w3, __half* __restrict__ o3) {
    if (blockIdx.x == 0) g_cnt[threadIdx.x] = 0;   // reset DAG counters
    int i = blockIdx.x * 256 + threadIdx.x;
    const float4* in;
    __half* out;
    int k;
    if (i < XN4) { in = x; out = xh; k = i; }
    else {
        int j = i - XN4;
        int w = j >> 18;           // / WN4
        k = j & (WN4 - 1);
        switch (w) {
            case 0: in = w0; out = o0; break;
            case 1: in = w1; out = o1; break;
            case 2: in = w2; out = o2; break;
            default: in = w3; out = o3; break;
        }
    }
    float4 v = in[k];
    *(__half2*)(out + (size_t)k * 4)     = __floats2half2_rn(v.x, v.y);
    *(__half2*)(out + (size_t)k * 4 + 2) = __floats2half2_rn(v.z, v.w);
}

// ---------------------------------------------------------------------------
// Launch
// ---------------------------------------------------------------------------
static void* sym(const void* s) { void* p; cudaGetSymbolAddress(&p, s); return p; }

extern "C" void kernel_launch(void* const* d_in, const int* in_sizes, int n_in,
                              void* d_out, int out_size) {
    const float* x  = (const float*)d_in[0];
    const float* Wq = (const float*)d_in[1];
    const float* bq = (const float*)d_in[2];
    const float* Wk = (const float*)d_in[3];
    const float* bk = (const float*)d_in[4];
    const float* Wv = (const float*)d_in[5];
    const float* bv = (const float*)d_in[6];
    const float* Wo = (const float*)d_in[7];
    const float* bo = (const float*)d_in[8];
    float* out = (float*)d_out;

    __half* xh  = (__half*)sym(g_xh);
    __half* Wqh = (__half*)sym(g_Wq);
    __half* Wkh = (__half*)sym(g_Wk);
    __half* Wvh = (__half*)sym(g_Wv);
    __half* Woh = (__half*)sym(g_Wo);

    cudaFuncSetAttribute(mega, cudaFuncAttributeMaxDynamicSharedMemorySize, SMEM_TOTAL);

    // convert + counter reset
    tohalf_all<<<(XN4 + 4 * WN4) / 256, 256>>>(
        (const float4*)x, xh, (const float4*)Wq, Wqh, (const float4*)Wk, Wkh,
        (const float4*)Wv, Wvh, (const float4*)Wo, Woh);

    // everything else: one DAG-scheduled launch
    MegaArgs ma;
    ma.x = x; ma.bq = bq; ma.bk = bk; ma.bv = bv; ma.bo = bo; ma.out = out;
    mega<<<MEGA_GRID, 256, SMEM_TOTAL>>>(ma);
}